// round 9
// baseline (speedup 1.0000x reference)
#include <cuda_runtime.h>
#include <cuda_bf16.h>
#include <math.h>
#include <stdint.h>

// ---------------- problem constants ----------------
#define BB   2
#define LSEQ 2048
#define DM   768
#define NH   12
#define HD   64
#define DFF  3072
#define MROWS (BB*LSEQ)      // 4096
#define NQKV  (3*DM)         // 2304
#define PLANE_ELEMS (BB*NH*LSEQ*HD)   // 3145728

// ---------------- scratch ----------------
__device__ float g_x1  [MROWS*DM];
__device__ __nv_bfloat16 g_h_h [MROWS*DM],  g_h_l [MROWS*DM];
__device__ __nv_bfloat16 g_at_h[MROWS*DM],  g_at_l[MROWS*DM];
__device__ __nv_bfloat16 g_ff_h[MROWS*DFF], g_ff_l[MROWS*DFF];
__device__ __nv_bfloat16 g_qh[PLANE_ELEMS];
__device__ __nv_bfloat16 g_kh[PLANE_ELEMS];
__device__ __nv_bfloat16 g_vh[PLANE_ELEMS];
__device__ __nv_bfloat16 g_wqkv_h[NQKV*DM], g_wqkv_l[NQKV*DM];
__device__ __nv_bfloat16 g_wout_h[DM*DM],   g_wout_l[DM*DM];
__device__ __nv_bfloat16 g_wfc1_h[DFF*DM],  g_wfc1_l[DFF*DM];
__device__ __nv_bfloat16 g_wfc2_h[DM*DFF],  g_wfc2_l[DM*DFF];

// ---------------- helpers ----------------
__device__ __forceinline__ uint32_t smem_u32(const void* p) {
    uint32_t a;
    asm("{ .reg .u64 t; cvta.to.shared.u64 t, %1; cvt.u32.u64 %0, t; }" : "=r"(a) : "l"(p));
    return a;
}
__device__ __forceinline__ void ldsm_x4(uint32_t* r, uint32_t addr) {
    asm volatile("ldmatrix.sync.aligned.m8n8.x4.shared.b16 {%0,%1,%2,%3}, [%4];"
        : "=r"(r[0]), "=r"(r[1]), "=r"(r[2]), "=r"(r[3]) : "r"(addr));
}
__device__ __forceinline__ void ldsm_x4_t(uint32_t* r, uint32_t addr) {
    asm volatile("ldmatrix.sync.aligned.m8n8.x4.trans.shared.b16 {%0,%1,%2,%3}, [%4];"
        : "=r"(r[0]), "=r"(r[1]), "=r"(r[2]), "=r"(r[3]) : "r"(addr));
}
__device__ __forceinline__ void mma2(float* d, const uint32_t* a, uint32_t b0, uint32_t b1) {
    asm volatile("mma.sync.aligned.m16n8k16.row.col.f32.bf16.bf16.f32 "
        "{%0,%1,%2,%3}, {%4,%5,%6,%7}, {%8,%9}, {%0,%1,%2,%3};"
        : "+f"(d[0]), "+f"(d[1]), "+f"(d[2]), "+f"(d[3])
        : "r"(a[0]), "r"(a[1]), "r"(a[2]), "r"(a[3]), "r"(b0), "r"(b1));
}
__device__ __forceinline__ void cp16(uint32_t s, const void* g) {
    asm volatile("cp.async.cg.shared.global [%0], [%1], 16;" :: "r"(s), "l"(g));
}
#define CP_COMMIT() asm volatile("cp.async.commit_group;" ::: "memory")
#define CP_WAIT(n)  asm volatile("cp.async.wait_group %0;" :: "n"(n) : "memory")

__device__ __forceinline__ void split2(float v, __nv_bfloat16& h, __nv_bfloat16& l) {
    h = __float2bfloat16(v);
    l = __float2bfloat16(v - __bfloat162float(h));
}
__device__ __forceinline__ uint32_t packf2(float lo, float hi) {
    uint32_t r;
    asm("cvt.rn.bf16x2.f32 %0, %1, %2;" : "=r"(r) : "f"(hi), "f"(lo));
    return r;
}

// ---------------- merged weight transpose + split ----------------
__global__ void wconv_all(const float* __restrict__ qkv_w, const float* __restrict__ out_w,
                          const float* __restrict__ fc1_w, const float* __restrict__ fc2_w) {
    __shared__ float t[32][33];
    int bid = blockIdx.x;
    const float* W; __nv_bfloat16 *Th, *Tl; int K, N, tile;
    if (bid < 1728)      { W = qkv_w; Th = g_wqkv_h; Tl = g_wqkv_l; K = DM;  N = NQKV; tile = bid; }
    else if (bid < 2304) { W = out_w; Th = g_wout_h; Tl = g_wout_l; K = DM;  N = DM;   tile = bid - 1728; }
    else if (bid < 4608) { W = fc1_w; Th = g_wfc1_h; Tl = g_wfc1_l; K = DM;  N = DFF;  tile = bid - 2304; }
    else                 { W = fc2_w; Th = g_wfc2_h; Tl = g_wfc2_l; K = DFF; N = DM;   tile = bid - 4608; }
    int ntx = N / 32;
    int n0 = (tile % ntx) * 32, k0 = (tile / ntx) * 32;
    int tx = threadIdx.x & 31, ty = threadIdx.x >> 5;
#pragma unroll
    for (int i = 0; i < 4; i++) {
        int k = ty + i * 8;
        t[k][tx] = W[(size_t)(k0 + k) * N + n0 + tx];
    }
    __syncthreads();
#pragma unroll
    for (int i = 0; i < 4; i++) {
        int nr = ty + i * 8;
        float v = t[tx][nr];
        __nv_bfloat16 h, l;
        split2(v, h, l);
        size_t o = (size_t)(n0 + nr) * K + k0 + tx;
        Th[o] = h; Tl[o] = l;
    }
}

// ---------------- LayerNorm: warp-per-row -> bf16 hi/lo planes ----------------
__global__ void ln_kernel(const float* __restrict__ X, const float* __restrict__ g,
                          const float* __restrict__ b,
                          __nv_bfloat16* __restrict__ Yh, __nv_bfloat16* __restrict__ Yl) {
    int w = threadIdx.x >> 5, lane = threadIdx.x & 31;
    int row = blockIdx.x * 8 + w;
    const float* xr = X + (size_t)row * DM;
    float4 v[6];
    float s = 0.f, sq = 0.f;
#pragma unroll
    for (int i = 0; i < 6; i++) {
        v[i] = *(const float4*)(xr + i * 128 + lane * 4);
        s  += v[i].x + v[i].y + v[i].z + v[i].w;
        sq += v[i].x * v[i].x + v[i].y * v[i].y + v[i].z * v[i].z + v[i].w * v[i].w;
    }
#pragma unroll
    for (int o = 16; o > 0; o >>= 1) {
        s  += __shfl_xor_sync(0xffffffffu, s, o);
        sq += __shfl_xor_sync(0xffffffffu, sq, o);
    }
    float mu  = s * (1.f / DM);
    float var = sq * (1.f / DM) - mu * mu;
    float inv = rsqrtf(var + 1e-5f);
#pragma unroll
    for (int i = 0; i < 6; i++) {
        int idx = i * 128 + lane * 4;
        float4 gg = *(const float4*)(g + idx);
        float4 bb = *(const float4*)(b + idx);
        float y0 = (v[i].x - mu) * inv * gg.x + bb.x;
        float y1 = (v[i].y - mu) * inv * gg.y + bb.y;
        float y2 = (v[i].z - mu) * inv * gg.z + bb.z;
        float y3 = (v[i].w - mu) * inv * gg.w + bb.w;
        __nv_bfloat16 h0, l0, h1, l1, h2, l2, h3, l3;
        split2(y0, h0, l0); split2(y1, h1, l1);
        split2(y2, h2, l2); split2(y3, h3, l3);
        size_t o = (size_t)row * DM + idx;
        uint2 hp, lp;
        hp.x = ((uint32_t)__bfloat16_as_ushort(h0)) | ((uint32_t)__bfloat16_as_ushort(h1) << 16);
        hp.y = ((uint32_t)__bfloat16_as_ushort(h2)) | ((uint32_t)__bfloat16_as_ushort(h3) << 16);
        lp.x = ((uint32_t)__bfloat16_as_ushort(l0)) | ((uint32_t)__bfloat16_as_ushort(l1) << 16);
        lp.y = ((uint32_t)__bfloat16_as_ushort(l2)) | ((uint32_t)__bfloat16_as_ushort(l3) << 16);
        *(uint2*)(Yh + o) = hp;
        *(uint2*)(Yl + o) = lp;
    }
}

// ---------------- HMMA GEMM: BM=128, BN=128, BK=32, 2-stage, 2 CTAs/SM -----
// warp grid 2x4, warp tile 64x32.
#define G_ST 80
#define GPLANE 10240                  // 128 rows * 80 B
#define GSTG (4 * GPLANE)             // 40960 (Ah, Al, Bh, Bl)
#define GSM (2 * GSTG)                // 81920

template <int MODE>
__global__ void __launch_bounds__(256, 2)
gemm_bf(const __nv_bfloat16* __restrict__ Ah, const __nv_bfloat16* __restrict__ Al,
        const __nv_bfloat16* __restrict__ Bh, const __nv_bfloat16* __restrict__ Bl,
        const float* __restrict__ bias, const float* __restrict__ res,
        float* __restrict__ C, __nv_bfloat16* __restrict__ Ch, __nv_bfloat16* __restrict__ Cl,
        int M, int N, int K) {
    extern __shared__ char smem[];
    const uint32_t sb = smem_u32(smem);

    int tid = threadIdx.x, wid = tid >> 5, lane = tid & 31;
    int bn = blockIdx.x, bm = blockIdx.y;
    int wm = wid >> 2, wn = wid & 3;

    uint32_t a_lm = (uint32_t)((wm * 64 + (lane & 15)) * G_ST + ((lane >> 4) & 1) * 16);
    uint32_t b_lm = (uint32_t)((wn * 32 + (lane & 15)) * G_ST + ((lane >> 4) & 1) * 16);

    float acc[4][4][4];
#pragma unroll
    for (int i = 0; i < 4; i++)
#pragma unroll
        for (int j = 0; j < 4; j++)
#pragma unroll
            for (int q = 0; q < 4; q++) acc[i][j][q] = 0.f;

    const int nkt = K / 32;

    // per-stage: 512 chunks per plane (128 rows x 4 x16B), 4 planes, 256 thr -> 8 cp16
    int r_c = tid >> 1, c_c = tid & 1;   // base: rows tid>>1 (0..127), col pairs
    auto load_stage = [&](int kt, int buf) {
        uint32_t st = sb + buf * GSTG;
        const __nv_bfloat16* a0 = Ah + (size_t)(bm * 128) * K + kt * 32;
        const __nv_bfloat16* a1 = Al + (size_t)(bm * 128) * K + kt * 32;
        const __nv_bfloat16* b0 = Bh + (size_t)(bn * 128) * K + kt * 32;
        const __nv_bfloat16* b1 = Bl + (size_t)(bn * 128) * K + kt * 32;
#pragma unroll
        for (int i = 0; i < 2; i++) {
            int col = c_c * 2 + i;            // 0..3 (16B units)
            uint32_t so = (uint32_t)(r_c * G_ST + col * 16);
            const size_t go = (size_t)r_c * K + col * 8;
            cp16(st + so, a0 + go);
            cp16(st + GPLANE + so, a1 + go);
            cp16(st + 2 * GPLANE + so, b0 + go);
            cp16(st + 3 * GPLANE + so, b1 + go);
        }
    };

    load_stage(0, 0); CP_COMMIT();
    if (nkt > 1) { load_stage(1, 1); CP_COMMIT(); }

    for (int kt = 0; kt < nkt; kt++) {
        if (kt + 1 < nkt) { CP_WAIT(1); } else { CP_WAIT(0); }
        __syncthreads();
        uint32_t st = sb + (kt & 1) * GSTG;
#pragma unroll
        for (int ks = 0; ks < 2; ks++) {
            // B fragments for this ks: 4 n8-tiles hi + lo
            uint32_t bh[4][2], bl[4][2];
#pragma unroll
            for (int nt2 = 0; nt2 < 2; nt2++) {
                uint32_t bo = b_lm + (uint32_t)(nt2 * 16 * G_ST + ks * 32);
                uint32_t th[4], tl[4];
                ldsm_x4(th, st + 2 * GPLANE + bo);
                ldsm_x4(tl, st + 3 * GPLANE + bo);
                bh[nt2 * 2][0] = th[0]; bh[nt2 * 2][1] = th[2];
                bh[nt2 * 2 + 1][0] = th[1]; bh[nt2 * 2 + 1][1] = th[3];
                bl[nt2 * 2][0] = tl[0]; bl[nt2 * 2][1] = tl[2];
                bl[nt2 * 2 + 1][0] = tl[1]; bl[nt2 * 2 + 1][1] = tl[3];
            }
            // A per-mt to bound register live range
#pragma unroll
            for (int mt = 0; mt < 4; mt++) {
                uint32_t ao = a_lm + (uint32_t)(mt * 16 * G_ST + ks * 32);
                uint32_t ah[4], al[4];
                ldsm_x4(ah, st + ao);
                ldsm_x4(al, st + GPLANE + ao);
#pragma unroll
                for (int nt = 0; nt < 4; nt++) {
                    mma2(acc[mt][nt], ah, bh[nt][0], bh[nt][1]);
                    mma2(acc[mt][nt], ah, bl[nt][0], bl[nt][1]);
                    mma2(acc[mt][nt], al, bh[nt][0], bh[nt][1]);
                }
            }
        }
        __syncthreads();
        if (kt + 2 < nkt) {
            load_stage(kt + 2, kt & 1);
            CP_COMMIT();
        }
    }

    int r0 = bm * 128 + wm * 64 + (lane >> 2);
    int c0 = bn * 128 + wn * 32 + (lane & 3) * 2;
#pragma unroll
    for (int mt = 0; mt < 4; mt++) {
#pragma unroll
        for (int nt = 0; nt < 4; nt++) {
            int col = c0 + nt * 8;
            float bb0 = bias[col], bb1 = bias[col + 1];
#pragma unroll
            for (int half = 0; half < 2; half++) {
                int row = r0 + mt * 16 + half * 8;
                float v0 = acc[mt][nt][half * 2 + 0] + bb0;
                float v1 = acc[mt][nt][half * 2 + 1] + bb1;
                if (MODE == 1) {
                    v0 = 0.5f * v0 * (1.f + erff(v0 * 0.70710678118654752f));
                    v1 = 0.5f * v1 * (1.f + erff(v1 * 0.70710678118654752f));
                    __nv_bfloat16 h0, l0, h1, l1;
                    split2(v0, h0, l0); split2(v1, h1, l1);
                    size_t o = (size_t)row * N + col;
                    __nv_bfloat162 hp; hp.x = h0; hp.y = h1;
                    __nv_bfloat162 lp; lp.x = l0; lp.y = l1;
                    *(__nv_bfloat162*)(Ch + o) = hp;
                    *(__nv_bfloat162*)(Cl + o) = lp;
                } else if (MODE == 2) {
                    const float* rp = res + (size_t)row * N + col;
                    float2 o; o.x = v0 + rp[0]; o.y = v1 + rp[1];
                    *(float2*)(C + (size_t)row * N + col) = o;
                } else { // MODE 3: scatter into Q/K/V bf16 planes
                    int i3 = col / DM;
                    int rem = col - i3 * DM;
                    int h = rem >> 6, d = rem & 63;
                    int bb = row >> 11, l = row & 2047;
                    size_t idx = (((size_t)bb * NH + h) * LSEQ + l) * HD + d;
                    if (i3 == 0) { v0 *= 0.125f; v1 *= 0.125f; }
                    __nv_bfloat162 hp;
                    hp.x = __float2bfloat16(v0); hp.y = __float2bfloat16(v1);
                    __nv_bfloat16* ph = (i3 == 0) ? g_qh : (i3 == 1) ? g_kh : g_vh;
                    *(__nv_bfloat162*)(ph + idx) = hp;
                }
            }
        }
    }
}

// ---------------- MMA flash attention: pure bf16, Q tile 128, 2 CTAs/SM ----
#define AT_ST 144
#define AT_PLANE (64 * AT_ST)          // 9216
#define AT_STAGE (2 * AT_PLANE)        // 18432 (K + V)
#define AT_SMEM (2 * AT_STAGE + 512)   // 37376
#define NT_KV (LSEQ / 64)              // 32

__global__ void __launch_bounds__(256, 2)
attn_mma(const int* __restrict__ mask,
         __nv_bfloat16* __restrict__ Oh, __nv_bfloat16* __restrict__ Ol) {
    extern __shared__ char sm[];
    const uint32_t sb = smem_u32(sm);
    float* mb2 = (float*)(sm + 2 * AT_STAGE);

    int tid = threadIdx.x, wid = tid >> 5, lane = tid & 31;
    int qt = blockIdx.x, h = blockIdx.y, b = blockIdx.z;
    size_t bh = ((size_t)b * NH + h) * LSEQ * HD;
    const __nv_bfloat16* Qp = g_qh + bh;
    const __nv_bfloat16* Kp = g_kh + bh;
    const __nv_bfloat16* Vp = g_vh + bh;

    {
        int qrow0 = qt * 128;
#pragma unroll
        for (int i = 0; i < 4; i++) {
            int c = tid * 4 + i;
            int row = c >> 3, col = c & 7;
            cp16(sb + (uint32_t)(row * AT_ST + col * 16),
                 Qp + (size_t)(qrow0 + row) * HD + col * 8);
        }
    }
    CP_COMMIT();
    CP_WAIT(0);
    __syncthreads();

    uint32_t qf[4][4];
    {
        uint32_t qbase = sb + (uint32_t)((wid * 16 + (lane & 15)) * AT_ST + (lane >> 4) * 16);
#pragma unroll
        for (int ks = 0; ks < 4; ks++)
            ldsm_x4(qf[ks], qbase + ks * 32);
    }
    __syncthreads();

    auto load_kv = [&](int kt, int buf) {
        uint32_t st = sb + buf * AT_STAGE;
        const __nv_bfloat16* k0 = Kp + (size_t)kt * 64 * HD;
        const __nv_bfloat16* v0 = Vp + (size_t)kt * 64 * HD;
#pragma unroll
        for (int i = 0; i < 2; i++) {
            int c = tid * 2 + i;
            int row = c >> 3, col = c & 7;
            uint32_t so = (uint32_t)(row * AT_ST + col * 16);
            cp16(st + so, k0 + (size_t)row * HD + col * 8);
            cp16(st + AT_PLANE + so, v0 + (size_t)row * HD + col * 8);
        }
    };

    if (tid < 64) mb2[tid] = mask[b * LSEQ + tid] ? 0.f : -1e30f;
    load_kv(0, 0);
    CP_COMMIT();

    float m0 = -1e30f, m1 = -1e30f, l0 = 0.f, l1 = 0.f;
    float o[8][4];
#pragma unroll
    for (int nt = 0; nt < 8; nt++)
#pragma unroll
        for (int q = 0; q < 4; q++) o[nt][q] = 0.f;

    for (int kt = 0; kt < NT_KV; kt++) {
        CP_WAIT(0);
        __syncthreads();
        if (kt + 1 < NT_KV) {
            if (tid < 64)
                mb2[((kt + 1) & 1) * 64 + tid] =
                    mask[b * LSEQ + (kt + 1) * 64 + tid] ? 0.f : -1e30f;
            load_kv(kt + 1, (kt + 1) & 1);
            CP_COMMIT();
        }
        uint32_t st = sb + (kt & 1) * AT_STAGE;
        const float* mrow = mb2 + (kt & 1) * 64;

        float s[8][4];
#pragma unroll
        for (int nt = 0; nt < 8; nt++)
#pragma unroll
            for (int q = 0; q < 4; q++) s[nt][q] = 0.f;

#pragma unroll
        for (int ks = 0; ks < 4; ks++) {
#pragma unroll
            for (int g = 0; g < 4; g++) {
                uint32_t addr = st + (uint32_t)((g * 16 + (lane & 15)) * AT_ST
                                                + ks * 32 + (lane >> 4) * 16);
                uint32_t t4[4];
                ldsm_x4(t4, addr);
                mma2(s[g * 2], qf[ks], t4[0], t4[2]);
                mma2(s[g * 2 + 1], qf[ks], t4[1], t4[3]);
            }
        }

        float rmax0 = -1e30f, rmax1 = -1e30f;
#pragma unroll
        for (int nt = 0; nt < 8; nt++) {
            int k0i = nt * 8 + (lane & 3) * 2;
            float mk0 = mrow[k0i], mk1 = mrow[k0i + 1];
            s[nt][0] += mk0; s[nt][1] += mk1;
            s[nt][2] += mk0; s[nt][3] += mk1;
            rmax0 = fmaxf(rmax0, fmaxf(s[nt][0], s[nt][1]));
            rmax1 = fmaxf(rmax1, fmaxf(s[nt][2], s[nt][3]));
        }
        rmax0 = fmaxf(rmax0, __shfl_xor_sync(0xffffffffu, rmax0, 1));
        rmax0 = fmaxf(rmax0, __shfl_xor_sync(0xffffffffu, rmax0, 2));
        rmax1 = fmaxf(rmax1, __shfl_xor_sync(0xffffffffu, rmax1, 1));
        rmax1 = fmaxf(rmax1, __shfl_xor_sync(0xffffffffu, rmax1, 2));
        float mn0 = fmaxf(m0, rmax0), mn1 = fmaxf(m1, rmax1);
        float al0 = __expf(m0 - mn0), al1 = __expf(m1 - mn1);
        m0 = mn0; m1 = mn1;
        float ps0 = 0.f, ps1 = 0.f;
#pragma unroll
        for (int nt = 0; nt < 8; nt++) {
            s[nt][0] = __expf(s[nt][0] - m0);
            s[nt][1] = __expf(s[nt][1] - m0);
            s[nt][2] = __expf(s[nt][2] - m1);
            s[nt][3] = __expf(s[nt][3] - m1);
            ps0 += s[nt][0] + s[nt][1];
            ps1 += s[nt][2] + s[nt][3];
        }
        ps0 += __shfl_xor_sync(0xffffffffu, ps0, 1);
        ps0 += __shfl_xor_sync(0xffffffffu, ps0, 2);
        ps1 += __shfl_xor_sync(0xffffffffu, ps1, 1);
        ps1 += __shfl_xor_sync(0xffffffffu, ps1, 2);
        l0 = l0 * al0 + ps0;
        l1 = l1 * al1 + ps1;
#pragma unroll
        for (int nt = 0; nt < 8; nt++) {
            o[nt][0] *= al0; o[nt][1] *= al0;
            o[nt][2] *= al1; o[nt][3] *= al1;
        }

        uint32_t pf[4][4];
#pragma unroll
        for (int j = 0; j < 4; j++) {
            pf[j][0] = packf2(s[2 * j][0], s[2 * j][1]);
            pf[j][1] = packf2(s[2 * j][2], s[2 * j][3]);
            pf[j][2] = packf2(s[2 * j + 1][0], s[2 * j + 1][1]);
            pf[j][3] = packf2(s[2 * j + 1][2], s[2 * j + 1][3]);
        }

        int g = lane >> 3;
#pragma unroll
        for (int j = 0; j < 4; j++) {
#pragma unroll
            for (int dt = 0; dt < 4; dt++) {
                uint32_t addr = st + (uint32_t)(AT_PLANE
                    + (j * 16 + (g >> 1) * 8 + (lane & 7)) * AT_ST
                    + dt * 32 + (g & 1) * 16);
                uint32_t t4[4];
                ldsm_x4_t(t4, addr);
                mma2(o[dt * 2], pf[j], t4[0], t4[2]);
                mma2(o[dt * 2 + 1], pf[j], t4[1], t4[3]);
            }
        }
    }

    float i0 = 1.f / l0, i1 = 1.f / l1;
    int rowg = b * LSEQ + qt * 128 + wid * 16 + (lane >> 2);
#pragma unroll
    for (int nt = 0; nt < 8; nt++) {
        int col = h * HD + nt * 8 + (lane & 3) * 2;
        float v0 = o[nt][0] * i0, v1 = o[nt][1] * i0;
        float v2 = o[nt][2] * i1, v3 = o[nt][3] * i1;
        __nv_bfloat16 h0, lo0, h1, lo1, h2, lo2, h3, lo3;
        split2(v0, h0, lo0); split2(v1, h1, lo1);
        split2(v2, h2, lo2); split2(v3, h3, lo3);
        __nv_bfloat162 hp0; hp0.x = h0; hp0.y = h1;
        __nv_bfloat162 lp0; lp0.x = lo0; lp0.y = lo1;
        __nv_bfloat162 hp1; hp1.x = h2; hp1.y = h3;
        __nv_bfloat162 lp1; lp1.x = lo2; lp1.y = lo3;
        *(__nv_bfloat162*)(Oh + (size_t)rowg * DM + col) = hp0;
        *(__nv_bfloat162*)(Ol + (size_t)rowg * DM + col) = lp0;
        *(__nv_bfloat162*)(Oh + (size_t)(rowg + 8) * DM + col) = hp1;
        *(__nv_bfloat162*)(Ol + (size_t)(rowg + 8) * DM + col) = lp1;
    }
}

// ---------------- launch ----------------
template <typename T>
static T* symaddr(const void* sym) {
    void* p = nullptr;
    cudaGetSymbolAddress(&p, sym);
    return (T*)p;
}

extern "C" void kernel_launch(void* const* d_in, const int* in_sizes, int n_in,
                              void* d_out, int out_size) {
    (void)in_sizes; (void)n_in; (void)out_size;
    const float* x      = (const float*)d_in[0];
    const int*   mask   = (const int*)  d_in[1];
    const float* ln1_g  = (const float*)d_in[2];
    const float* ln1_b  = (const float*)d_in[3];
    const float* qkv_w  = (const float*)d_in[4];
    const float* qkv_b  = (const float*)d_in[5];
    const float* out_w  = (const float*)d_in[6];
    const float* out_b  = (const float*)d_in[7];
    const float* ln2_g  = (const float*)d_in[8];
    const float* ln2_b  = (const float*)d_in[9];
    const float* fc1_w  = (const float*)d_in[10];
    const float* fc1_b  = (const float*)d_in[11];
    const float* fc2_w  = (const float*)d_in[12];
    const float* fc2_b  = (const float*)d_in[13];
    float* out = (float*)d_out;

    float* p_x1  = symaddr<float>(g_x1);
    __nv_bfloat16* p_hh  = symaddr<__nv_bfloat16>(g_h_h);
    __nv_bfloat16* p_hl  = symaddr<__nv_bfloat16>(g_h_l);
    __nv_bfloat16* p_ath = symaddr<__nv_bfloat16>(g_at_h);
    __nv_bfloat16* p_atl = symaddr<__nv_bfloat16>(g_at_l);
    __nv_bfloat16* p_ffh = symaddr<__nv_bfloat16>(g_ff_h);
    __nv_bfloat16* p_ffl = symaddr<__nv_bfloat16>(g_ff_l);
    __nv_bfloat16* wq_h = symaddr<__nv_bfloat16>(g_wqkv_h), *wq_l = symaddr<__nv_bfloat16>(g_wqkv_l);
    __nv_bfloat16* wo_h = symaddr<__nv_bfloat16>(g_wout_h), *wo_l = symaddr<__nv_bfloat16>(g_wout_l);
    __nv_bfloat16* w1_h = symaddr<__nv_bfloat16>(g_wfc1_h), *w1_l = symaddr<__nv_bfloat16>(g_wfc1_l);
    __nv_bfloat16* w2_h = symaddr<__nv_bfloat16>(g_wfc2_h), *w2_l = symaddr<__nv_bfloat16>(g_wfc2_l);

    cudaFuncSetAttribute(gemm_bf<1>, cudaFuncAttributeMaxDynamicSharedMemorySize, GSM);
    cudaFuncSetAttribute(gemm_bf<2>, cudaFuncAttributeMaxDynamicSharedMemorySize, GSM);
    cudaFuncSetAttribute(gemm_bf<3>, cudaFuncAttributeMaxDynamicSharedMemorySize, GSM);
    cudaFuncSetAttribute(attn_mma, cudaFuncAttributeMaxDynamicSharedMemorySize, AT_SMEM);

    // 1. LN1
    ln_kernel<<<MROWS / 8, 256>>>(x, ln1_g, ln1_b, p_hh, p_hl);
    // 2. merged weight conversions
    wconv_all<<<6912, 256>>>(qkv_w, out_w, fc1_w, fc2_w);
    // 3. QKV projection -> Q/K/V bf16 planes (Q pre-scaled)
    gemm_bf<3><<<dim3(NQKV / 128, MROWS / 128), 256, GSM>>>(
        p_hh, p_hl, wq_h, wq_l, qkv_b, nullptr, nullptr, nullptr, nullptr, MROWS, NQKV, DM);
    // 4. MMA flash attention -> bf16 hi/lo planes
    attn_mma<<<dim3(LSEQ / 128, NH, BB), 256, AT_SMEM>>>(mask, p_ath, p_atl);
    // 5. output projection + residual
    gemm_bf<2><<<dim3(DM / 128, MROWS / 128), 256, GSM>>>(
        p_ath, p_atl, wo_h, wo_l, out_b, x, p_x1, nullptr, nullptr, MROWS, DM, DM);
    // 6. LN2
    ln_kernel<<<MROWS / 8, 256>>>(p_x1, ln2_g, ln2_b, p_hh, p_hl);
    // 7. fc1 + GELU -> bf16 planes
    gemm_bf<1><<<dim3(DFF / 128, MROWS / 128), 256, GSM>>>(
        p_hh, p_hl, w1_h, w1_l, fc1_b, nullptr, nullptr, p_ffh, p_ffl, MROWS, DFF, DM);
    // 8. fc2 + residual -> output
    gemm_bf<2><<<dim3(DM / 128, MROWS / 128), 256, GSM>>>(
        p_ffh, p_ffl, w2_h, w2_l, fc2_b, p_x1, out, nullptr, nullptr, MROWS, DM, DFF);
}

// round 10
// speedup vs baseline: 1.3240x; 1.3240x over previous
#include <cuda_runtime.h>
#include <cuda_bf16.h>
#include <math.h>
#include <stdint.h>

// ---------------- problem constants ----------------
#define BB   2
#define LSEQ 2048
#define DM   768
#define NH   12
#define HD   64
#define DFF  3072
#define MROWS (BB*LSEQ)      // 4096
#define NQKV  (3*DM)         // 2304
#define PLANE_ELEMS (BB*NH*LSEQ*HD)   // 3145728

// ---------------- scratch ----------------
__device__ float g_x1  [MROWS*DM];
__device__ __nv_bfloat16 g_h_h [MROWS*DM],  g_h_l [MROWS*DM];
__device__ __nv_bfloat16 g_at_h[MROWS*DM];
__device__ __nv_bfloat16 g_ff_h[MROWS*DFF], g_ff_l[MROWS*DFF];
__device__ __nv_bfloat16 g_qh[PLANE_ELEMS];
__device__ __nv_bfloat16 g_kh[PLANE_ELEMS];
__device__ __nv_bfloat16 g_vh[PLANE_ELEMS];
__device__ __nv_bfloat16 g_wqkv_h[NQKV*DM], g_wqkv_l[NQKV*DM];
__device__ __nv_bfloat16 g_wout_h[DM*DM],   g_wout_l[DM*DM];
__device__ __nv_bfloat16 g_wfc1_h[DFF*DM],  g_wfc1_l[DFF*DM];
__device__ __nv_bfloat16 g_wfc2_h[DM*DFF],  g_wfc2_l[DM*DFF];

// ---------------- helpers ----------------
__device__ __forceinline__ uint32_t smem_u32(const void* p) {
    uint32_t a;
    asm("{ .reg .u64 t; cvta.to.shared.u64 t, %1; cvt.u32.u64 %0, t; }" : "=r"(a) : "l"(p));
    return a;
}
__device__ __forceinline__ void ldsm_x4(uint32_t* r, uint32_t addr) {
    asm volatile("ldmatrix.sync.aligned.m8n8.x4.shared.b16 {%0,%1,%2,%3}, [%4];"
        : "=r"(r[0]), "=r"(r[1]), "=r"(r[2]), "=r"(r[3]) : "r"(addr));
}
__device__ __forceinline__ void ldsm_x4_t(uint32_t* r, uint32_t addr) {
    asm volatile("ldmatrix.sync.aligned.m8n8.x4.trans.shared.b16 {%0,%1,%2,%3}, [%4];"
        : "=r"(r[0]), "=r"(r[1]), "=r"(r[2]), "=r"(r[3]) : "r"(addr));
}
__device__ __forceinline__ void mma2(float* d, const uint32_t* a, uint32_t b0, uint32_t b1) {
    asm volatile("mma.sync.aligned.m16n8k16.row.col.f32.bf16.bf16.f32 "
        "{%0,%1,%2,%3}, {%4,%5,%6,%7}, {%8,%9}, {%0,%1,%2,%3};"
        : "+f"(d[0]), "+f"(d[1]), "+f"(d[2]), "+f"(d[3])
        : "r"(a[0]), "r"(a[1]), "r"(a[2]), "r"(a[3]), "r"(b0), "r"(b1));
}
__device__ __forceinline__ void cp16(uint32_t s, const void* g) {
    asm volatile("cp.async.cg.shared.global [%0], [%1], 16;" :: "r"(s), "l"(g));
}
#define CP_COMMIT() asm volatile("cp.async.commit_group;" ::: "memory")
#define CP_WAIT(n)  asm volatile("cp.async.wait_group %0;" :: "n"(n) : "memory")

__device__ __forceinline__ void split2(float v, __nv_bfloat16& h, __nv_bfloat16& l) {
    h = __float2bfloat16(v);
    l = __float2bfloat16(v - __bfloat162float(h));
}
__device__ __forceinline__ uint32_t packf2(float lo, float hi) {
    uint32_t r;
    asm("cvt.rn.bf16x2.f32 %0, %1, %2;" : "=r"(r) : "f"(hi), "f"(lo));
    return r;
}

// ---------------- merged weight transpose + split ----------------
__global__ void wconv_all(const float* __restrict__ qkv_w, const float* __restrict__ out_w,
                          const float* __restrict__ fc1_w, const float* __restrict__ fc2_w) {
    __shared__ float t[32][33];
    int bid = blockIdx.x;
    const float* W; __nv_bfloat16 *Th, *Tl; int K, N, tile;
    if (bid < 1728)      { W = qkv_w; Th = g_wqkv_h; Tl = g_wqkv_l; K = DM;  N = NQKV; tile = bid; }
    else if (bid < 2304) { W = out_w; Th = g_wout_h; Tl = g_wout_l; K = DM;  N = DM;   tile = bid - 1728; }
    else if (bid < 4608) { W = fc1_w; Th = g_wfc1_h; Tl = g_wfc1_l; K = DM;  N = DFF;  tile = bid - 2304; }
    else                 { W = fc2_w; Th = g_wfc2_h; Tl = g_wfc2_l; K = DFF; N = DM;   tile = bid - 4608; }
    int ntx = N / 32;
    int n0 = (tile % ntx) * 32, k0 = (tile / ntx) * 32;
    int tx = threadIdx.x & 31, ty = threadIdx.x >> 5;
#pragma unroll
    for (int i = 0; i < 4; i++) {
        int k = ty + i * 8;
        t[k][tx] = W[(size_t)(k0 + k) * N + n0 + tx];
    }
    __syncthreads();
#pragma unroll
    for (int i = 0; i < 4; i++) {
        int nr = ty + i * 8;
        float v = t[tx][nr];
        __nv_bfloat16 h, l;
        split2(v, h, l);
        size_t o = (size_t)(n0 + nr) * K + k0 + tx;
        Th[o] = h; Tl[o] = l;
    }
}

// ---------------- LayerNorm: warp-per-row -> bf16 hi/lo planes ----------------
__global__ void ln_kernel(const float* __restrict__ X, const float* __restrict__ g,
                          const float* __restrict__ b,
                          __nv_bfloat16* __restrict__ Yh, __nv_bfloat16* __restrict__ Yl) {
    int w = threadIdx.x >> 5, lane = threadIdx.x & 31;
    int row = blockIdx.x * 8 + w;
    const float* xr = X + (size_t)row * DM;
    float4 v[6];
    float s = 0.f, sq = 0.f;
#pragma unroll
    for (int i = 0; i < 6; i++) {
        v[i] = *(const float4*)(xr + i * 128 + lane * 4);
        s  += v[i].x + v[i].y + v[i].z + v[i].w;
        sq += v[i].x * v[i].x + v[i].y * v[i].y + v[i].z * v[i].z + v[i].w * v[i].w;
    }
#pragma unroll
    for (int o = 16; o > 0; o >>= 1) {
        s  += __shfl_xor_sync(0xffffffffu, s, o);
        sq += __shfl_xor_sync(0xffffffffu, sq, o);
    }
    float mu  = s * (1.f / DM);
    float var = sq * (1.f / DM) - mu * mu;
    float inv = rsqrtf(var + 1e-5f);
#pragma unroll
    for (int i = 0; i < 6; i++) {
        int idx = i * 128 + lane * 4;
        float4 gg = *(const float4*)(g + idx);
        float4 bb = *(const float4*)(b + idx);
        float y0 = (v[i].x - mu) * inv * gg.x + bb.x;
        float y1 = (v[i].y - mu) * inv * gg.y + bb.y;
        float y2 = (v[i].z - mu) * inv * gg.z + bb.z;
        float y3 = (v[i].w - mu) * inv * gg.w + bb.w;
        __nv_bfloat16 h0, l0, h1, l1, h2, l2, h3, l3;
        split2(y0, h0, l0); split2(y1, h1, l1);
        split2(y2, h2, l2); split2(y3, h3, l3);
        size_t o = (size_t)row * DM + idx;
        uint2 hp, lp;
        hp.x = ((uint32_t)__bfloat16_as_ushort(h0)) | ((uint32_t)__bfloat16_as_ushort(h1) << 16);
        hp.y = ((uint32_t)__bfloat16_as_ushort(h2)) | ((uint32_t)__bfloat16_as_ushort(h3) << 16);
        lp.x = ((uint32_t)__bfloat16_as_ushort(l0)) | ((uint32_t)__bfloat16_as_ushort(l1) << 16);
        lp.y = ((uint32_t)__bfloat16_as_ushort(l2)) | ((uint32_t)__bfloat16_as_ushort(l3) << 16);
        *(uint2*)(Yh + o) = hp;
        *(uint2*)(Yl + o) = lp;
    }
}

// ---------------- HMMA GEMM: BM=128, BN=64, BK=64, 2-stage, 2 CTAs/SM ------
// (R8 configuration; NT=2 drops the Al term for attention-diluted GEMMs)
#define A_ST2 144
#define APLANE 18432           // 128*144
#define BPLANE 9216            // 64*144
#define STG (2*APLANE + 2*BPLANE)   // 55296
#define GSM (2 * STG)               // 110592

template <int MODE, int NT>
__global__ void __launch_bounds__(256, 2)
gemm_bf(const __nv_bfloat16* __restrict__ Ah, const __nv_bfloat16* __restrict__ Al,
        const __nv_bfloat16* __restrict__ Bh, const __nv_bfloat16* __restrict__ Bl,
        const float* __restrict__ bias, const float* __restrict__ res,
        float* __restrict__ C, __nv_bfloat16* __restrict__ Ch, __nv_bfloat16* __restrict__ Cl,
        int M, int N, int K) {
    extern __shared__ char smem[];
    const uint32_t sb = smem_u32(smem);

    int tid = threadIdx.x, wid = tid >> 5, lane = tid & 31;
    int bn = blockIdx.x, bm = blockIdx.y;
    int wm = wid >> 2, wn = wid & 3;

    uint32_t a_lm = (uint32_t)((wm * 64 + (lane & 15)) * A_ST2 + ((lane >> 4) & 1) * 16);
    uint32_t b_lm = (uint32_t)((wn * 16 + (lane & 15)) * A_ST2 + ((lane >> 4) & 1) * 16);

    float acc[4][2][4];
#pragma unroll
    for (int i = 0; i < 4; i++)
#pragma unroll
        for (int j = 0; j < 2; j++)
#pragma unroll
            for (int q = 0; q < 4; q++) acc[i][j][q] = 0.f;

    const int nkt = K / 64;

    auto load_stage = [&](int kt, int buf) {
        uint32_t st = sb + buf * STG;
        const __nv_bfloat16* a0 = Ah + (size_t)(bm * 128) * K + kt * 64;
        const __nv_bfloat16* b0 = Bh + (size_t)(bn * 64) * K + kt * 64;
        const __nv_bfloat16* b1 = Bl + (size_t)(bn * 64) * K + kt * 64;
#pragma unroll
        for (int i = 0; i < 4; i++) {
            int c = tid + i * 256;
            int row = c >> 3, col = c & 7;
            uint32_t so = (uint32_t)(row * A_ST2 + col * 16);
            cp16(st + so, a0 + (size_t)row * K + col * 8);
        }
        if (NT == 3) {
            const __nv_bfloat16* a1 = Al + (size_t)(bm * 128) * K + kt * 64;
#pragma unroll
            for (int i = 0; i < 4; i++) {
                int c = tid + i * 256;
                int row = c >> 3, col = c & 7;
                uint32_t so = (uint32_t)(row * A_ST2 + col * 16);
                cp16(st + APLANE + so, a1 + (size_t)row * K + col * 8);
            }
        }
#pragma unroll
        for (int i = 0; i < 2; i++) {
            int c = tid + i * 256;
            int row = c >> 3, col = c & 7;
            uint32_t so = (uint32_t)(row * A_ST2 + col * 16);
            cp16(st + 2 * APLANE + so, b0 + (size_t)row * K + col * 8);
            cp16(st + 2 * APLANE + BPLANE + so, b1 + (size_t)row * K + col * 8);
        }
    };

    load_stage(0, 0); CP_COMMIT();
    if (nkt > 1) { load_stage(1, 1); CP_COMMIT(); }

    for (int kt = 0; kt < nkt; kt++) {
        if (kt + 1 < nkt) { CP_WAIT(1); } else { CP_WAIT(0); }
        __syncthreads();
        uint32_t st = sb + (kt & 1) * STG;
#pragma unroll
        for (int ks = 0; ks < 4; ks++) {
            uint32_t ah[4][4], al[4][4], th[4], tl[4];
#pragma unroll
            for (int mt = 0; mt < 4; mt++) {
                uint32_t ao = a_lm + (uint32_t)(mt * 16 * A_ST2 + ks * 32);
                ldsm_x4(ah[mt], st + ao);
                if (NT == 3) ldsm_x4(al[mt], st + APLANE + ao);
            }
            uint32_t bo = b_lm + (uint32_t)(ks * 32);
            ldsm_x4(th, st + 2 * APLANE + bo);
            ldsm_x4(tl, st + 2 * APLANE + BPLANE + bo);
#pragma unroll
            for (int mt = 0; mt < 4; mt++) {
                mma2(acc[mt][0], ah[mt], th[0], th[2]);
                mma2(acc[mt][0], ah[mt], tl[0], tl[2]);
                if (NT == 3) mma2(acc[mt][0], al[mt], th[0], th[2]);
                mma2(acc[mt][1], ah[mt], th[1], th[3]);
                mma2(acc[mt][1], ah[mt], tl[1], tl[3]);
                if (NT == 3) mma2(acc[mt][1], al[mt], th[1], th[3]);
            }
        }
        __syncthreads();
        if (kt + 2 < nkt) {
            load_stage(kt + 2, kt & 1);
            CP_COMMIT();
        }
    }

    int r0 = bm * 128 + wm * 64 + (lane >> 2);
    int c0 = bn * 64 + wn * 16 + (lane & 3) * 2;
#pragma unroll
    for (int mt = 0; mt < 4; mt++) {
#pragma unroll
        for (int nt = 0; nt < 2; nt++) {
            int col = c0 + nt * 8;
            float bb0 = bias[col], bb1 = bias[col + 1];
#pragma unroll
            for (int half = 0; half < 2; half++) {
                int row = r0 + mt * 16 + half * 8;
                float v0 = acc[mt][nt][half * 2 + 0] + bb0;
                float v1 = acc[mt][nt][half * 2 + 1] + bb1;
                if (MODE == 1) {
                    v0 = 0.5f * v0 * (1.f + erff(v0 * 0.70710678118654752f));
                    v1 = 0.5f * v1 * (1.f + erff(v1 * 0.70710678118654752f));
                    __nv_bfloat16 h0, l0, h1, l1;
                    split2(v0, h0, l0); split2(v1, h1, l1);
                    size_t o = (size_t)row * N + col;
                    __nv_bfloat162 hp; hp.x = h0; hp.y = h1;
                    __nv_bfloat162 lp; lp.x = l0; lp.y = l1;
                    *(__nv_bfloat162*)(Ch + o) = hp;
                    *(__nv_bfloat162*)(Cl + o) = lp;
                } else if (MODE == 2) {
                    const float* rp = res + (size_t)row * N + col;
                    float2 o; o.x = v0 + rp[0]; o.y = v1 + rp[1];
                    *(float2*)(C + (size_t)row * N + col) = o;
                } else { // MODE 3: scatter into Q/K/V bf16 planes
                    int i3 = col / DM;
                    int rem = col - i3 * DM;
                    int h = rem >> 6, d = rem & 63;
                    int bb = row >> 11, l = row & 2047;
                    size_t idx = (((size_t)bb * NH + h) * LSEQ + l) * HD + d;
                    if (i3 == 0) { v0 *= 0.125f; v1 *= 0.125f; }
                    __nv_bfloat162 hp;
                    hp.x = __float2bfloat16(v0); hp.y = __float2bfloat16(v1);
                    __nv_bfloat16* ph = (i3 == 0) ? g_qh : (i3 == 1) ? g_kh : g_vh;
                    *(__nv_bfloat162*)(ph + idx) = hp;
                }
            }
        }
    }
}

// ---------------- MMA flash attention: pure bf16, Q tile 128, 2 CTAs/SM ----
#define AT_ST 144
#define AT_PLANE (64 * AT_ST)          // 9216
#define AT_STAGE (2 * AT_PLANE)        // 18432 (K + V)
#define AT_SMEM (2 * AT_STAGE + 512)   // 37376
#define NT_KV (LSEQ / 64)              // 32

__global__ void __launch_bounds__(256, 2)
attn_mma(const int* __restrict__ mask, __nv_bfloat16* __restrict__ Oh) {
    extern __shared__ char sm[];
    const uint32_t sb = smem_u32(sm);
    float* mb2 = (float*)(sm + 2 * AT_STAGE);

    int tid = threadIdx.x, wid = tid >> 5, lane = tid & 31;
    int qt = blockIdx.x, h = blockIdx.y, b = blockIdx.z;
    size_t bh = ((size_t)b * NH + h) * LSEQ * HD;
    const __nv_bfloat16* Qp = g_qh + bh;
    const __nv_bfloat16* Kp = g_kh + bh;
    const __nv_bfloat16* Vp = g_vh + bh;

    {
        int qrow0 = qt * 128;
#pragma unroll
        for (int i = 0; i < 4; i++) {
            int c = tid * 4 + i;
            int row = c >> 3, col = c & 7;
            cp16(sb + (uint32_t)(row * AT_ST + col * 16),
                 Qp + (size_t)(qrow0 + row) * HD + col * 8);
        }
    }
    CP_COMMIT();
    CP_WAIT(0);
    __syncthreads();

    uint32_t qf[4][4];
    {
        uint32_t qbase = sb + (uint32_t)((wid * 16 + (lane & 15)) * AT_ST + (lane >> 4) * 16);
#pragma unroll
        for (int ks = 0; ks < 4; ks++)
            ldsm_x4(qf[ks], qbase + ks * 32);
    }
    __syncthreads();

    auto load_kv = [&](int kt, int buf) {
        uint32_t st = sb + buf * AT_STAGE;
        const __nv_bfloat16* k0 = Kp + (size_t)kt * 64 * HD;
        const __nv_bfloat16* v0 = Vp + (size_t)kt * 64 * HD;
#pragma unroll
        for (int i = 0; i < 2; i++) {
            int c = tid * 2 + i;
            int row = c >> 3, col = c & 7;
            uint32_t so = (uint32_t)(row * AT_ST + col * 16);
            cp16(st + so, k0 + (size_t)row * HD + col * 8);
            cp16(st + AT_PLANE + so, v0 + (size_t)row * HD + col * 8);
        }
    };

    if (tid < 64) mb2[tid] = mask[b * LSEQ + tid] ? 0.f : -1e30f;
    load_kv(0, 0);
    CP_COMMIT();

    float m0 = -1e30f, m1 = -1e30f, l0 = 0.f, l1 = 0.f;
    float o[8][4];
#pragma unroll
    for (int nt = 0; nt < 8; nt++)
#pragma unroll
        for (int q = 0; q < 4; q++) o[nt][q] = 0.f;

    for (int kt = 0; kt < NT_KV; kt++) {
        CP_WAIT(0);
        __syncthreads();
        if (kt + 1 < NT_KV) {
            if (tid < 64)
                mb2[((kt + 1) & 1) * 64 + tid] =
                    mask[b * LSEQ + (kt + 1) * 64 + tid] ? 0.f : -1e30f;
            load_kv(kt + 1, (kt + 1) & 1);
            CP_COMMIT();
        }
        uint32_t st = sb + (kt & 1) * AT_STAGE;
        const float* mrow = mb2 + (kt & 1) * 64;

        float s[8][4];
#pragma unroll
        for (int nt = 0; nt < 8; nt++)
#pragma unroll
            for (int q = 0; q < 4; q++) s[nt][q] = 0.f;

#pragma unroll
        for (int ks = 0; ks < 4; ks++) {
#pragma unroll
            for (int g = 0; g < 4; g++) {
                uint32_t addr = st + (uint32_t)((g * 16 + (lane & 15)) * AT_ST
                                                + ks * 32 + (lane >> 4) * 16);
                uint32_t t4[4];
                ldsm_x4(t4, addr);
                mma2(s[g * 2], qf[ks], t4[0], t4[2]);
                mma2(s[g * 2 + 1], qf[ks], t4[1], t4[3]);
            }
        }

        float rmax0 = -1e30f, rmax1 = -1e30f;
#pragma unroll
        for (int nt = 0; nt < 8; nt++) {
            int k0i = nt * 8 + (lane & 3) * 2;
            float mk0 = mrow[k0i], mk1 = mrow[k0i + 1];
            s[nt][0] += mk0; s[nt][1] += mk1;
            s[nt][2] += mk0; s[nt][3] += mk1;
            rmax0 = fmaxf(rmax0, fmaxf(s[nt][0], s[nt][1]));
            rmax1 = fmaxf(rmax1, fmaxf(s[nt][2], s[nt][3]));
        }
        rmax0 = fmaxf(rmax0, __shfl_xor_sync(0xffffffffu, rmax0, 1));
        rmax0 = fmaxf(rmax0, __shfl_xor_sync(0xffffffffu, rmax0, 2));
        rmax1 = fmaxf(rmax1, __shfl_xor_sync(0xffffffffu, rmax1, 1));
        rmax1 = fmaxf(rmax1, __shfl_xor_sync(0xffffffffu, rmax1, 2));
        float mn0 = fmaxf(m0, rmax0), mn1 = fmaxf(m1, rmax1);
        float al0 = __expf(m0 - mn0), al1 = __expf(m1 - mn1);
        m0 = mn0; m1 = mn1;
        float ps0 = 0.f, ps1 = 0.f;
#pragma unroll
        for (int nt = 0; nt < 8; nt++) {
            s[nt][0] = __expf(s[nt][0] - m0);
            s[nt][1] = __expf(s[nt][1] - m0);
            s[nt][2] = __expf(s[nt][2] - m1);
            s[nt][3] = __expf(s[nt][3] - m1);
            ps0 += s[nt][0] + s[nt][1];
            ps1 += s[nt][2] + s[nt][3];
        }
        ps0 += __shfl_xor_sync(0xffffffffu, ps0, 1);
        ps0 += __shfl_xor_sync(0xffffffffu, ps0, 2);
        ps1 += __shfl_xor_sync(0xffffffffu, ps1, 1);
        ps1 += __shfl_xor_sync(0xffffffffu, ps1, 2);
        l0 = l0 * al0 + ps0;
        l1 = l1 * al1 + ps1;
        // rescale only when some row's max changed (al != 1 exactly otherwise)
        bool need = (al0 != 1.f) || (al1 != 1.f);
        if (__ballot_sync(0xffffffffu, need)) {
#pragma unroll
            for (int nt = 0; nt < 8; nt++) {
                o[nt][0] *= al0; o[nt][1] *= al0;
                o[nt][2] *= al1; o[nt][3] *= al1;
            }
        }

        uint32_t pf[4][4];
#pragma unroll
        for (int j = 0; j < 4; j++) {
            pf[j][0] = packf2(s[2 * j][0], s[2 * j][1]);
            pf[j][1] = packf2(s[2 * j][2], s[2 * j][3]);
            pf[j][2] = packf2(s[2 * j + 1][0], s[2 * j + 1][1]);
            pf[j][3] = packf2(s[2 * j + 1][2], s[2 * j + 1][3]);
        }

        int g = lane >> 3;
#pragma unroll
        for (int j = 0; j < 4; j++) {
#pragma unroll
            for (int dt = 0; dt < 4; dt++) {
                uint32_t addr = st + (uint32_t)(AT_PLANE
                    + (j * 16 + (g >> 1) * 8 + (lane & 7)) * AT_ST
                    + dt * 32 + (g & 1) * 16);
                uint32_t t4[4];
                ldsm_x4_t(t4, addr);
                mma2(o[dt * 2], pf[j], t4[0], t4[2]);
                mma2(o[dt * 2 + 1], pf[j], t4[1], t4[3]);
            }
        }
    }

    // ---- finalize: O /= l -> bf16 hi plane only
    float i0 = 1.f / l0, i1 = 1.f / l1;
    int rowg = b * LSEQ + qt * 128 + wid * 16 + (lane >> 2);
#pragma unroll
    for (int nt = 0; nt < 8; nt++) {
        int col = h * HD + nt * 8 + (lane & 3) * 2;
        uint32_t hp0 = packf2(o[nt][0] * i0, o[nt][1] * i0);
        uint32_t hp1 = packf2(o[nt][2] * i1, o[nt][3] * i1);
        *(uint32_t*)(Oh + (size_t)rowg * DM + col) = hp0;
        *(uint32_t*)(Oh + (size_t)(rowg + 8) * DM + col) = hp1;
    }
}

// ---------------- launch ----------------
template <typename T>
static T* symaddr(const void* sym) {
    void* p = nullptr;
    cudaGetSymbolAddress(&p, sym);
    return (T*)p;
}

extern "C" void kernel_launch(void* const* d_in, const int* in_sizes, int n_in,
                              void* d_out, int out_size) {
    (void)in_sizes; (void)n_in; (void)out_size;
    const float* x      = (const float*)d_in[0];
    const int*   mask   = (const int*)  d_in[1];
    const float* ln1_g  = (const float*)d_in[2];
    const float* ln1_b  = (const float*)d_in[3];
    const float* qkv_w  = (const float*)d_in[4];
    const float* qkv_b  = (const float*)d_in[5];
    const float* out_w  = (const float*)d_in[6];
    const float* out_b  = (const float*)d_in[7];
    const float* ln2_g  = (const float*)d_in[8];
    const float* ln2_b  = (const float*)d_in[9];
    const float* fc1_w  = (const float*)d_in[10];
    const float* fc1_b  = (const float*)d_in[11];
    const float* fc2_w  = (const float*)d_in[12];
    const float* fc2_b  = (const float*)d_in[13];
    float* out = (float*)d_out;

    float* p_x1  = symaddr<float>(g_x1);
    __nv_bfloat16* p_hh  = symaddr<__nv_bfloat16>(g_h_h);
    __nv_bfloat16* p_hl  = symaddr<__nv_bfloat16>(g_h_l);
    __nv_bfloat16* p_ath = symaddr<__nv_bfloat16>(g_at_h);
    __nv_bfloat16* p_ffh = symaddr<__nv_bfloat16>(g_ff_h);
    __nv_bfloat16* p_ffl = symaddr<__nv_bfloat16>(g_ff_l);
    __nv_bfloat16* wq_h = symaddr<__nv_bfloat16>(g_wqkv_h), *wq_l = symaddr<__nv_bfloat16>(g_wqkv_l);
    __nv_bfloat16* wo_h = symaddr<__nv_bfloat16>(g_wout_h), *wo_l = symaddr<__nv_bfloat16>(g_wout_l);
    __nv_bfloat16* w1_h = symaddr<__nv_bfloat16>(g_wfc1_h), *w1_l = symaddr<__nv_bfloat16>(g_wfc1_l);
    __nv_bfloat16* w2_h = symaddr<__nv_bfloat16>(g_wfc2_h), *w2_l = symaddr<__nv_bfloat16>(g_wfc2_l);

    cudaFuncSetAttribute((const void*)gemm_bf<1, 3>, cudaFuncAttributeMaxDynamicSharedMemorySize, GSM);
    cudaFuncSetAttribute((const void*)gemm_bf<2, 2>, cudaFuncAttributeMaxDynamicSharedMemorySize, GSM);
    cudaFuncSetAttribute((const void*)gemm_bf<2, 3>, cudaFuncAttributeMaxDynamicSharedMemorySize, GSM);
    cudaFuncSetAttribute((const void*)gemm_bf<3, 2>, cudaFuncAttributeMaxDynamicSharedMemorySize, GSM);
    cudaFuncSetAttribute((const void*)attn_mma, cudaFuncAttributeMaxDynamicSharedMemorySize, AT_SMEM);

    // 1. LN1
    ln_kernel<<<MROWS / 8, 256>>>(x, ln1_g, ln1_b, p_hh, p_hl);
    // 2. merged weight conversions
    wconv_all<<<6912, 256>>>(qkv_w, out_w, fc1_w, fc2_w);
    // 3. QKV projection (2-term: attention path is dilution-protected)
    gemm_bf<3, 2><<<dim3(NQKV / 64, MROWS / 128), 256, GSM>>>(
        p_hh, nullptr, wq_h, wq_l, qkv_b, nullptr, nullptr, nullptr, nullptr, MROWS, NQKV, DM);
    // 4. MMA flash attention -> bf16 hi plane
    attn_mma<<<dim3(LSEQ / 128, NH, BB), 256, AT_SMEM>>>(mask, p_ath);
    // 5. output projection + residual (2-term)
    gemm_bf<2, 2><<<dim3(DM / 64, MROWS / 128), 256, GSM>>>(
        p_ath, nullptr, wo_h, wo_l, out_b, x, p_x1, nullptr, nullptr, MROWS, DM, DM);
    // 6. LN2
    ln_kernel<<<MROWS / 8, 256>>>(p_x1, ln2_g, ln2_b, p_hh, p_hl);
    // 7. fc1 + GELU (3-term) -> bf16 planes
    gemm_bf<1, 3><<<dim3(DFF / 64, MROWS / 128), 256, GSM>>>(
        p_hh, p_hl, w1_h, w1_l, fc1_b, nullptr, nullptr, p_ffh, p_ffl, MROWS, DFF, DM);
    // 8. fc2 + residual (3-term) -> output
    gemm_bf<2, 3><<<dim3(DM / 64, MROWS / 128), 256, GSM>>>(
        p_ffh, p_ffl, w2_h, w2_l, fc2_b, p_x1, out, nullptr, nullptr, MROWS, DM, DFF);
}

// round 11
// speedup vs baseline: 1.7109x; 1.2923x over previous
#include <cuda_runtime.h>
#include <cuda_fp16.h>
#include <math.h>
#include <stdint.h>

// ---------------- problem constants ----------------
#define BB   2
#define LSEQ 2048
#define DM   768
#define NH   12
#define HD   64
#define DFF  3072
#define MROWS (BB*LSEQ)      // 4096
#define NQKV  (3*DM)         // 2304
#define PLANE_ELEMS (BB*NH*LSEQ*HD)   // 3145728
#define QSCALE 0.1803368801111204f   // 0.125 * log2(e)

// ---------------- scratch ----------------
__device__ float g_x1  [MROWS*DM];
__device__ __half g_h_h [MROWS*DM];
__device__ __half g_at_h[MROWS*DM];
__device__ __half g_ff_h[MROWS*DFF];
__device__ __half g_qh[PLANE_ELEMS];
__device__ __half g_kh[PLANE_ELEMS];
__device__ __half g_vh[PLANE_ELEMS];
__device__ __half g_wqkv_h[NQKV*DM], g_wqkv_l[NQKV*DM];
__device__ __half g_wout_h[DM*DM],   g_wout_l[DM*DM];
__device__ __half g_wfc1_h[DFF*DM],  g_wfc1_l[DFF*DM];
__device__ __half g_wfc2_h[DM*DFF],  g_wfc2_l[DM*DFF];

// ---------------- helpers ----------------
__device__ __forceinline__ uint32_t smem_u32(const void* p) {
    uint32_t a;
    asm("{ .reg .u64 t; cvta.to.shared.u64 t, %1; cvt.u32.u64 %0, t; }" : "=r"(a) : "l"(p));
    return a;
}
__device__ __forceinline__ void ldsm_x4(uint32_t* r, uint32_t addr) {
    asm volatile("ldmatrix.sync.aligned.m8n8.x4.shared.b16 {%0,%1,%2,%3}, [%4];"
        : "=r"(r[0]), "=r"(r[1]), "=r"(r[2]), "=r"(r[3]) : "r"(addr));
}
__device__ __forceinline__ void ldsm_x4_t(uint32_t* r, uint32_t addr) {
    asm volatile("ldmatrix.sync.aligned.m8n8.x4.trans.shared.b16 {%0,%1,%2,%3}, [%4];"
        : "=r"(r[0]), "=r"(r[1]), "=r"(r[2]), "=r"(r[3]) : "r"(addr));
}
__device__ __forceinline__ void mma2(float* d, const uint32_t* a, uint32_t b0, uint32_t b1) {
    asm volatile("mma.sync.aligned.m16n8k16.row.col.f32.f16.f16.f32 "
        "{%0,%1,%2,%3}, {%4,%5,%6,%7}, {%8,%9}, {%0,%1,%2,%3};"
        : "+f"(d[0]), "+f"(d[1]), "+f"(d[2]), "+f"(d[3])
        : "r"(a[0]), "r"(a[1]), "r"(a[2]), "r"(a[3]), "r"(b0), "r"(b1));
}
__device__ __forceinline__ void cp16(uint32_t s, const void* g) {
    asm volatile("cp.async.cg.shared.global [%0], [%1], 16;" :: "r"(s), "l"(g));
}
#define CP_COMMIT() asm volatile("cp.async.commit_group;" ::: "memory")
#define CP_WAIT(n)  asm volatile("cp.async.wait_group %0;" :: "n"(n) : "memory")

__device__ __forceinline__ void split2h(float v, __half& h, __half& l) {
    h = __float2half(v);
    l = __float2half(v - __half2float(h));
}
__device__ __forceinline__ uint32_t packh2(float lo, float hi) {
    __half2 p = __floats2half2_rn(lo, hi);
    return *reinterpret_cast<uint32_t*>(&p);
}
__device__ __forceinline__ float ex2f(float x) {
    float r;
    asm("ex2.approx.ftz.f32 %0, %1;" : "=f"(r) : "f"(x));
    return r;
}

// ---------------- merged weight transpose + split (fp16 hi/lo) -------------
__global__ void wconv_all(const float* __restrict__ qkv_w, const float* __restrict__ out_w,
                          const float* __restrict__ fc1_w, const float* __restrict__ fc2_w) {
    __shared__ float t[32][33];
    int bid = blockIdx.x;
    const float* W; __half *Th, *Tl; int K, N, tile;
    if (bid < 1728)      { W = qkv_w; Th = g_wqkv_h; Tl = g_wqkv_l; K = DM;  N = NQKV; tile = bid; }
    else if (bid < 2304) { W = out_w; Th = g_wout_h; Tl = g_wout_l; K = DM;  N = DM;   tile = bid - 1728; }
    else if (bid < 4608) { W = fc1_w; Th = g_wfc1_h; Tl = g_wfc1_l; K = DM;  N = DFF;  tile = bid - 2304; }
    else                 { W = fc2_w; Th = g_wfc2_h; Tl = g_wfc2_l; K = DFF; N = DM;   tile = bid - 4608; }
    int ntx = N / 32;
    int n0 = (tile % ntx) * 32, k0 = (tile / ntx) * 32;
    int tx = threadIdx.x & 31, ty = threadIdx.x >> 5;
#pragma unroll
    for (int i = 0; i < 4; i++) {
        int k = ty + i * 8;
        t[k][tx] = W[(size_t)(k0 + k) * N + n0 + tx];
    }
    __syncthreads();
#pragma unroll
    for (int i = 0; i < 4; i++) {
        int nr = ty + i * 8;
        float v = t[tx][nr];
        __half h, l;
        split2h(v, h, l);
        size_t o = (size_t)(n0 + nr) * K + k0 + tx;
        Th[o] = h; Tl[o] = l;
    }
}

// ---------------- LayerNorm: warp-per-row -> fp16 plane ----------------
__global__ void ln_kernel(const float* __restrict__ X, const float* __restrict__ g,
                          const float* __restrict__ b, __half* __restrict__ Yh) {
    int w = threadIdx.x >> 5, lane = threadIdx.x & 31;
    int row = blockIdx.x * 8 + w;
    const float* xr = X + (size_t)row * DM;
    float4 v[6];
    float s = 0.f, sq = 0.f;
#pragma unroll
    for (int i = 0; i < 6; i++) {
        v[i] = *(const float4*)(xr + i * 128 + lane * 4);
        s  += v[i].x + v[i].y + v[i].z + v[i].w;
        sq += v[i].x * v[i].x + v[i].y * v[i].y + v[i].z * v[i].z + v[i].w * v[i].w;
    }
#pragma unroll
    for (int o = 16; o > 0; o >>= 1) {
        s  += __shfl_xor_sync(0xffffffffu, s, o);
        sq += __shfl_xor_sync(0xffffffffu, sq, o);
    }
    float mu  = s * (1.f / DM);
    float var = sq * (1.f / DM) - mu * mu;
    float inv = rsqrtf(var + 1e-5f);
#pragma unroll
    for (int i = 0; i < 6; i++) {
        int idx = i * 128 + lane * 4;
        float4 gg = *(const float4*)(g + idx);
        float4 bb = *(const float4*)(b + idx);
        float y0 = (v[i].x - mu) * inv * gg.x + bb.x;
        float y1 = (v[i].y - mu) * inv * gg.y + bb.y;
        float y2 = (v[i].z - mu) * inv * gg.z + bb.z;
        float y3 = (v[i].w - mu) * inv * gg.w + bb.w;
        uint2 hp;
        hp.x = packh2(y0, y1);
        hp.y = packh2(y2, y3);
        *(uint2*)(Yh + (size_t)row * DM + idx) = hp;
    }
}

// ---------------- fp16 GEMM: BM=128, BN=64, BK=64, 2-stage, 2 CTAs/SM ------
// D = A * (Wh + Wl), fp32 acc. A single fp16 plane; W hi/lo fp16.
#define A_ST2 144
#define APLANE 18432           // 128*144
#define BPLANE 9216            // 64*144
#define STG (APLANE + 2*BPLANE)     // 36864
#define GSM (2 * STG)               // 73728

template <int MODE>
__global__ void __launch_bounds__(256, 2)
gemm_fp(const __half* __restrict__ A,
        const __half* __restrict__ Bh, const __half* __restrict__ Bl,
        const float* __restrict__ bias, const float* __restrict__ res,
        float* __restrict__ C, __half* __restrict__ Ch,
        int M, int N, int K) {
    extern __shared__ char smem[];
    const uint32_t sb = smem_u32(smem);

    int tid = threadIdx.x, wid = tid >> 5, lane = tid & 31;
    int bn = blockIdx.x, bm = blockIdx.y;
    int wm = wid >> 2, wn = wid & 3;

    uint32_t a_lm = (uint32_t)((wm * 64 + (lane & 15)) * A_ST2 + ((lane >> 4) & 1) * 16);
    uint32_t b_lm = (uint32_t)((wn * 16 + (lane & 15)) * A_ST2 + ((lane >> 4) & 1) * 16);

    float acc[4][2][4];
#pragma unroll
    for (int i = 0; i < 4; i++)
#pragma unroll
        for (int j = 0; j < 2; j++)
#pragma unroll
            for (int q = 0; q < 4; q++) acc[i][j][q] = 0.f;

    const int nkt = K / 64;

    auto load_stage = [&](int kt, int buf) {
        uint32_t st = sb + buf * STG;
        const __half* a0 = A + (size_t)(bm * 128) * K + kt * 64;
        const __half* b0 = Bh + (size_t)(bn * 64) * K + kt * 64;
        const __half* b1 = Bl + (size_t)(bn * 64) * K + kt * 64;
#pragma unroll
        for (int i = 0; i < 4; i++) {
            int c = tid + i * 256;
            int row = c >> 3, col = c & 7;
            uint32_t so = (uint32_t)(row * A_ST2 + col * 16);
            cp16(st + so, a0 + (size_t)row * K + col * 8);
        }
#pragma unroll
        for (int i = 0; i < 2; i++) {
            int c = tid + i * 256;
            int row = c >> 3, col = c & 7;
            uint32_t so = (uint32_t)(row * A_ST2 + col * 16);
            cp16(st + APLANE + so, b0 + (size_t)row * K + col * 8);
            cp16(st + APLANE + BPLANE + so, b1 + (size_t)row * K + col * 8);
        }
    };

    load_stage(0, 0); CP_COMMIT();
    if (nkt > 1) { load_stage(1, 1); CP_COMMIT(); }

    for (int kt = 0; kt < nkt; kt++) {
        if (kt + 1 < nkt) { CP_WAIT(1); } else { CP_WAIT(0); }
        __syncthreads();
        uint32_t st = sb + (kt & 1) * STG;
#pragma unroll
        for (int ks = 0; ks < 4; ks++) {
            uint32_t ah[4][4], th[4], tl[4];
#pragma unroll
            for (int mt = 0; mt < 4; mt++) {
                uint32_t ao = a_lm + (uint32_t)(mt * 16 * A_ST2 + ks * 32);
                ldsm_x4(ah[mt], st + ao);
            }
            uint32_t bo = b_lm + (uint32_t)(ks * 32);
            ldsm_x4(th, st + APLANE + bo);
            ldsm_x4(tl, st + APLANE + BPLANE + bo);
#pragma unroll
            for (int mt = 0; mt < 4; mt++) {
                mma2(acc[mt][0], ah[mt], th[0], th[2]);
                mma2(acc[mt][0], ah[mt], tl[0], tl[2]);
                mma2(acc[mt][1], ah[mt], th[1], th[3]);
                mma2(acc[mt][1], ah[mt], tl[1], tl[3]);
            }
        }
        __syncthreads();
        if (kt + 2 < nkt) {
            load_stage(kt + 2, kt & 1);
            CP_COMMIT();
        }
    }

    int r0 = bm * 128 + wm * 64 + (lane >> 2);
    int c0 = bn * 64 + wn * 16 + (lane & 3) * 2;
#pragma unroll
    for (int mt = 0; mt < 4; mt++) {
#pragma unroll
        for (int nt = 0; nt < 2; nt++) {
            int col = c0 + nt * 8;
            float bb0 = bias[col], bb1 = bias[col + 1];
#pragma unroll
            for (int half_ = 0; half_ < 2; half_++) {
                int row = r0 + mt * 16 + half_ * 8;
                float v0 = acc[mt][nt][half_ * 2 + 0] + bb0;
                float v1 = acc[mt][nt][half_ * 2 + 1] + bb1;
                if (MODE == 1) {
                    v0 = 0.5f * v0 * (1.f + erff(v0 * 0.70710678118654752f));
                    v1 = 0.5f * v1 * (1.f + erff(v1 * 0.70710678118654752f));
                    *(uint32_t*)(Ch + (size_t)row * N + col) = packh2(v0, v1);
                } else if (MODE == 2) {
                    const float* rp = res + (size_t)row * N + col;
                    float2 o; o.x = v0 + rp[0]; o.y = v1 + rp[1];
                    *(float2*)(C + (size_t)row * N + col) = o;
                } else { // MODE 3: scatter into Q/K/V fp16 planes
                    int i3 = col / DM;
                    int rem = col - i3 * DM;
                    int h = rem >> 6, d = rem & 63;
                    int bb = row >> 11, l = row & 2047;
                    size_t idx = (((size_t)bb * NH + h) * LSEQ + l) * HD + d;
                    if (i3 == 0) { v0 *= QSCALE; v1 *= QSCALE; }
                    __half* ph = (i3 == 0) ? g_qh : (i3 == 1) ? g_kh : g_vh;
                    *(uint32_t*)(ph + idx) = packh2(v0, v1);
                }
            }
        }
    }
}

// ---------------- MMA flash attention: fp16, Q tile 128, 2 CTAs/SM ---------
// Scores are in log2 domain (Q pre-scaled by 0.125*log2e); softmax uses ex2.
#define AT_ST 144
#define AT_PLANE (64 * AT_ST)          // 9216
#define AT_STAGE (2 * AT_PLANE)        // 18432 (K + V)
#define AT_SMEM (2 * AT_STAGE + 512)   // 37376
#define NT_KV (LSEQ / 64)              // 32

__global__ void __launch_bounds__(256, 2)
attn_mma(const int* __restrict__ mask, __half* __restrict__ Oh) {
    extern __shared__ char sm[];
    const uint32_t sb = smem_u32(sm);
    float* mb2 = (float*)(sm + 2 * AT_STAGE);

    int tid = threadIdx.x, wid = tid >> 5, lane = tid & 31;
    int qt = blockIdx.x, h = blockIdx.y, b = blockIdx.z;
    size_t bh = ((size_t)b * NH + h) * LSEQ * HD;
    const __half* Qp = g_qh + bh;
    const __half* Kp = g_kh + bh;
    const __half* Vp = g_vh + bh;

    {
        int qrow0 = qt * 128;
#pragma unroll
        for (int i = 0; i < 4; i++) {
            int c = tid * 4 + i;
            int row = c >> 3, col = c & 7;
            cp16(sb + (uint32_t)(row * AT_ST + col * 16),
                 Qp + (size_t)(qrow0 + row) * HD + col * 8);
        }
    }
    CP_COMMIT();
    CP_WAIT(0);
    __syncthreads();

    uint32_t qf[4][4];
    {
        uint32_t qbase = sb + (uint32_t)((wid * 16 + (lane & 15)) * AT_ST + (lane >> 4) * 16);
#pragma unroll
        for (int ks = 0; ks < 4; ks++)
            ldsm_x4(qf[ks], qbase + ks * 32);
    }
    __syncthreads();

    auto load_kv = [&](int kt, int buf) {
        uint32_t st = sb + buf * AT_STAGE;
        const __half* k0 = Kp + (size_t)kt * 64 * HD;
        const __half* v0 = Vp + (size_t)kt * 64 * HD;
#pragma unroll
        for (int i = 0; i < 2; i++) {
            int c = tid * 2 + i;
            int row = c >> 3, col = c & 7;
            uint32_t so = (uint32_t)(row * AT_ST + col * 16);
            cp16(st + so, k0 + (size_t)row * HD + col * 8);
            cp16(st + AT_PLANE + so, v0 + (size_t)row * HD + col * 8);
        }
    };

    if (tid < 64) mb2[tid] = mask[b * LSEQ + tid] ? 0.f : -1e30f;
    load_kv(0, 0);
    CP_COMMIT();

    float m0 = -1e30f, m1 = -1e30f, l0 = 0.f, l1 = 0.f;
    float o[8][4];
#pragma unroll
    for (int nt = 0; nt < 8; nt++)
#pragma unroll
        for (int q = 0; q < 4; q++) o[nt][q] = 0.f;

    for (int kt = 0; kt < NT_KV; kt++) {
        CP_WAIT(0);
        __syncthreads();
        if (kt + 1 < NT_KV) {
            if (tid < 64)
                mb2[((kt + 1) & 1) * 64 + tid] =
                    mask[b * LSEQ + (kt + 1) * 64 + tid] ? 0.f : -1e30f;
            load_kv(kt + 1, (kt + 1) & 1);
            CP_COMMIT();
        }
        uint32_t st = sb + (kt & 1) * AT_STAGE;
        const float* mrow = mb2 + (kt & 1) * 64;

        float s[8][4];
#pragma unroll
        for (int nt = 0; nt < 8; nt++)
#pragma unroll
            for (int q = 0; q < 4; q++) s[nt][q] = 0.f;

#pragma unroll
        for (int ks = 0; ks < 4; ks++) {
#pragma unroll
            for (int g = 0; g < 4; g++) {
                uint32_t addr = st + (uint32_t)((g * 16 + (lane & 15)) * AT_ST
                                                + ks * 32 + (lane >> 4) * 16);
                uint32_t t4[4];
                ldsm_x4(t4, addr);
                mma2(s[g * 2], qf[ks], t4[0], t4[2]);
                mma2(s[g * 2 + 1], qf[ks], t4[1], t4[3]);
            }
        }

        float rmax0 = -1e30f, rmax1 = -1e30f;
#pragma unroll
        for (int nt = 0; nt < 8; nt++) {
            int k0i = nt * 8 + (lane & 3) * 2;
            float mk0 = mrow[k0i], mk1 = mrow[k0i + 1];
            s[nt][0] += mk0; s[nt][1] += mk1;
            s[nt][2] += mk0; s[nt][3] += mk1;
            rmax0 = fmaxf(rmax0, fmaxf(s[nt][0], s[nt][1]));
            rmax1 = fmaxf(rmax1, fmaxf(s[nt][2], s[nt][3]));
        }
        rmax0 = fmaxf(rmax0, __shfl_xor_sync(0xffffffffu, rmax0, 1));
        rmax0 = fmaxf(rmax0, __shfl_xor_sync(0xffffffffu, rmax0, 2));
        rmax1 = fmaxf(rmax1, __shfl_xor_sync(0xffffffffu, rmax1, 1));
        rmax1 = fmaxf(rmax1, __shfl_xor_sync(0xffffffffu, rmax1, 2));
        float mn0 = fmaxf(m0, rmax0), mn1 = fmaxf(m1, rmax1);
        float al0 = ex2f(m0 - mn0), al1 = ex2f(m1 - mn1);
        m0 = mn0; m1 = mn1;
        float ps0 = 0.f, ps1 = 0.f;
#pragma unroll
        for (int nt = 0; nt < 8; nt++) {
            s[nt][0] = ex2f(s[nt][0] - m0);
            s[nt][1] = ex2f(s[nt][1] - m0);
            s[nt][2] = ex2f(s[nt][2] - m1);
            s[nt][3] = ex2f(s[nt][3] - m1);
            ps0 += s[nt][0] + s[nt][1];
            ps1 += s[nt][2] + s[nt][3];
        }
        ps0 += __shfl_xor_sync(0xffffffffu, ps0, 1);
        ps0 += __shfl_xor_sync(0xffffffffu, ps0, 2);
        ps1 += __shfl_xor_sync(0xffffffffu, ps1, 1);
        ps1 += __shfl_xor_sync(0xffffffffu, ps1, 2);
        l0 = l0 * al0 + ps0;
        l1 = l1 * al1 + ps1;
        bool need = (al0 != 1.f) || (al1 != 1.f);
        if (__ballot_sync(0xffffffffu, need)) {
#pragma unroll
            for (int nt = 0; nt < 8; nt++) {
                o[nt][0] *= al0; o[nt][1] *= al0;
                o[nt][2] *= al1; o[nt][3] *= al1;
            }
        }

        uint32_t pf[4][4];
#pragma unroll
        for (int j = 0; j < 4; j++) {
            pf[j][0] = packh2(s[2 * j][0], s[2 * j][1]);
            pf[j][1] = packh2(s[2 * j][2], s[2 * j][3]);
            pf[j][2] = packh2(s[2 * j + 1][0], s[2 * j + 1][1]);
            pf[j][3] = packh2(s[2 * j + 1][2], s[2 * j + 1][3]);
        }

        int g = lane >> 3;
#pragma unroll
        for (int j = 0; j < 4; j++) {
#pragma unroll
            for (int dt = 0; dt < 4; dt++) {
                uint32_t addr = st + (uint32_t)(AT_PLANE
                    + (j * 16 + (g >> 1) * 8 + (lane & 7)) * AT_ST
                    + dt * 32 + (g & 1) * 16);
                uint32_t t4[4];
                ldsm_x4_t(t4, addr);
                mma2(o[dt * 2], pf[j], t4[0], t4[2]);
                mma2(o[dt * 2 + 1], pf[j], t4[1], t4[3]);
            }
        }
    }

    float i0 = 1.f / l0, i1 = 1.f / l1;
    int rowg = b * LSEQ + qt * 128 + wid * 16 + (lane >> 2);
#pragma unroll
    for (int nt = 0; nt < 8; nt++) {
        int col = h * HD + nt * 8 + (lane & 3) * 2;
        *(uint32_t*)(Oh + (size_t)rowg * DM + col) = packh2(o[nt][0] * i0, o[nt][1] * i0);
        *(uint32_t*)(Oh + (size_t)(rowg + 8) * DM + col) = packh2(o[nt][2] * i1, o[nt][3] * i1);
    }
}

// ---------------- launch ----------------
template <typename T>
static T* symaddr(const void* sym) {
    void* p = nullptr;
    cudaGetSymbolAddress(&p, sym);
    return (T*)p;
}

extern "C" void kernel_launch(void* const* d_in, const int* in_sizes, int n_in,
                              void* d_out, int out_size) {
    (void)in_sizes; (void)n_in; (void)out_size;
    const float* x      = (const float*)d_in[0];
    const int*   mask   = (const int*)  d_in[1];
    const float* ln1_g  = (const float*)d_in[2];
    const float* ln1_b  = (const float*)d_in[3];
    const float* qkv_w  = (const float*)d_in[4];
    const float* qkv_b  = (const float*)d_in[5];
    const float* out_w  = (const float*)d_in[6];
    const float* out_b  = (const float*)d_in[7];
    const float* ln2_g  = (const float*)d_in[8];
    const float* ln2_b  = (const float*)d_in[9];
    const float* fc1_w  = (const float*)d_in[10];
    const float* fc1_b  = (const float*)d_in[11];
    const float* fc2_w  = (const float*)d_in[12];
    const float* fc2_b  = (const float*)d_in[13];
    float* out = (float*)d_out;

    float* p_x1  = symaddr<float>(g_x1);
    __half* p_hh  = symaddr<__half>(g_h_h);
    __half* p_ath = symaddr<__half>(g_at_h);
    __half* p_ffh = symaddr<__half>(g_ff_h);
    __half* wq_h = symaddr<__half>(g_wqkv_h), *wq_l = symaddr<__half>(g_wqkv_l);
    __half* wo_h = symaddr<__half>(g_wout_h), *wo_l = symaddr<__half>(g_wout_l);
    __half* w1_h = symaddr<__half>(g_wfc1_h), *w1_l = symaddr<__half>(g_wfc1_l);
    __half* w2_h = symaddr<__half>(g_wfc2_h), *w2_l = symaddr<__half>(g_wfc2_l);

    cudaFuncSetAttribute((const void*)gemm_fp<1>, cudaFuncAttributeMaxDynamicSharedMemorySize, GSM);
    cudaFuncSetAttribute((const void*)gemm_fp<2>, cudaFuncAttributeMaxDynamicSharedMemorySize, GSM);
    cudaFuncSetAttribute((const void*)gemm_fp<3>, cudaFuncAttributeMaxDynamicSharedMemorySize, GSM);
    cudaFuncSetAttribute((const void*)attn_mma, cudaFuncAttributeMaxDynamicSharedMemorySize, AT_SMEM);

    // 1. LN1 -> fp16 plane
    ln_kernel<<<MROWS / 8, 256>>>(x, ln1_g, ln1_b, p_hh);
    // 2. merged weight conversions (fp16 hi/lo)
    wconv_all<<<6912, 256>>>(qkv_w, out_w, fc1_w, fc2_w);
    // 3. QKV projection -> Q/K/V fp16 planes (Q scaled by 0.125*log2e)
    gemm_fp<3><<<dim3(NQKV / 64, MROWS / 128), 256, GSM>>>(
        p_hh, wq_h, wq_l, qkv_b, nullptr, nullptr, nullptr, MROWS, NQKV, DM);
    // 4. MMA flash attention -> fp16 plane
    attn_mma<<<dim3(LSEQ / 128, NH, BB), 256, AT_SMEM>>>(mask, p_ath);
    // 5. output projection + residual
    gemm_fp<2><<<dim3(DM / 64, MROWS / 128), 256, GSM>>>(
        p_ath, wo_h, wo_l, out_b, x, p_x1, nullptr, MROWS, DM, DM);
    // 6. LN2
    ln_kernel<<<MROWS / 8, 256>>>(p_x1, ln2_g, ln2_b, p_hh);
    // 7. fc1 + GELU -> fp16 plane
    gemm_fp<1><<<dim3(DFF / 64, MROWS / 128), 256, GSM>>>(
        p_hh, w1_h, w1_l, fc1_b, nullptr, nullptr, p_ffh, MROWS, DFF, DM);
    // 8. fc2 + residual -> output
    gemm_fp<2><<<dim3(DM / 64, MROWS / 128), 256, GSM>>>(
        p_ffh, w2_h, w2_l, fc2_b, p_x1, out, nullptr, MROWS, DM, DFF);
}

// round 12
// speedup vs baseline: 2.3528x; 1.3752x over previous
#include <cuda_runtime.h>
#include <cuda_fp16.h>
#include <math.h>
#include <stdint.h>

// ---------------- problem constants ----------------
#define BB   2
#define LSEQ 2048
#define DM   768
#define NH   12
#define HD   64
#define DFF  3072
#define MROWS (BB*LSEQ)      // 4096
#define NQKV  (3*DM)         // 2304
#define PLANE_ELEMS (BB*NH*LSEQ*HD)   // 3145728
#define QSCALE 0.1803368801111204f   // 0.125 * log2(e)

// ---------------- scratch ----------------
__device__ float g_x1  [MROWS*DM];
__device__ __half g_h_h [MROWS*DM];
__device__ __half g_at_h[MROWS*DM];
__device__ __half g_ff_h[MROWS*DFF];
__device__ __half g_qh[PLANE_ELEMS];
__device__ __half g_kh[PLANE_ELEMS];
__device__ __half g_vh[PLANE_ELEMS];
__device__ __half g_wqkv_h[NQKV*DM];
__device__ __half g_wout_h[DM*DM];
__device__ __half g_wfc1_h[DFF*DM];
__device__ __half g_wfc2_h[DM*DFF];

// ---------------- helpers ----------------
__device__ __forceinline__ uint32_t smem_u32(const void* p) {
    uint32_t a;
    asm("{ .reg .u64 t; cvta.to.shared.u64 t, %1; cvt.u32.u64 %0, t; }" : "=r"(a) : "l"(p));
    return a;
}
__device__ __forceinline__ void ldsm_x4(uint32_t* r, uint32_t addr) {
    asm volatile("ldmatrix.sync.aligned.m8n8.x4.shared.b16 {%0,%1,%2,%3}, [%4];"
        : "=r"(r[0]), "=r"(r[1]), "=r"(r[2]), "=r"(r[3]) : "r"(addr));
}
__device__ __forceinline__ void ldsm_x4_t(uint32_t* r, uint32_t addr) {
    asm volatile("ldmatrix.sync.aligned.m8n8.x4.trans.shared.b16 {%0,%1,%2,%3}, [%4];"
        : "=r"(r[0]), "=r"(r[1]), "=r"(r[2]), "=r"(r[3]) : "r"(addr));
}
__device__ __forceinline__ void mma2(float* d, const uint32_t* a, uint32_t b0, uint32_t b1) {
    asm volatile("mma.sync.aligned.m16n8k16.row.col.f32.f16.f16.f32 "
        "{%0,%1,%2,%3}, {%4,%5,%6,%7}, {%8,%9}, {%0,%1,%2,%3};"
        : "+f"(d[0]), "+f"(d[1]), "+f"(d[2]), "+f"(d[3])
        : "r"(a[0]), "r"(a[1]), "r"(a[2]), "r"(a[3]), "r"(b0), "r"(b1));
}
__device__ __forceinline__ void cp16(uint32_t s, const void* g) {
    asm volatile("cp.async.cg.shared.global [%0], [%1], 16;" :: "r"(s), "l"(g));
}
#define CP_COMMIT() asm volatile("cp.async.commit_group;" ::: "memory")
#define CP_WAIT(n)  asm volatile("cp.async.wait_group %0;" :: "n"(n) : "memory")

__device__ __forceinline__ uint32_t packh2(float lo, float hi) {
    __half2 p = __floats2half2_rn(lo, hi);
    return *reinterpret_cast<uint32_t*>(&p);
}
__device__ __forceinline__ float ex2f(float x) {
    float r;
    asm("ex2.approx.ftz.f32 %0, %1;" : "=f"(r) : "f"(x));
    return r;
}

// ---------------- merged weight transpose (fp16 hi only) -------------------
__global__ void wconv_all(const float* __restrict__ qkv_w, const float* __restrict__ out_w,
                          const float* __restrict__ fc1_w, const float* __restrict__ fc2_w) {
    __shared__ float t[32][33];
    int bid = blockIdx.x;
    const float* W; __half *Th; int K, N, tile;
    if (bid < 1728)      { W = qkv_w; Th = g_wqkv_h; K = DM;  N = NQKV; tile = bid; }
    else if (bid < 2304) { W = out_w; Th = g_wout_h; K = DM;  N = DM;   tile = bid - 1728; }
    else if (bid < 4608) { W = fc1_w; Th = g_wfc1_h; K = DM;  N = DFF;  tile = bid - 2304; }
    else                 { W = fc2_w; Th = g_wfc2_h; K = DFF; N = DM;   tile = bid - 4608; }
    int ntx = N / 32;
    int n0 = (tile % ntx) * 32, k0 = (tile / ntx) * 32;
    int tx = threadIdx.x & 31, ty = threadIdx.x >> 5;
#pragma unroll
    for (int i = 0; i < 4; i++) {
        int k = ty + i * 8;
        t[k][tx] = W[(size_t)(k0 + k) * N + n0 + tx];
    }
    __syncthreads();
#pragma unroll
    for (int i = 0; i < 4; i++) {
        int nr = ty + i * 8;
        Th[(size_t)(n0 + nr) * K + k0 + tx] = __float2half(t[tx][nr]);
    }
}

// ---------------- LayerNorm: warp-per-row -> fp16 plane ----------------
__global__ void ln_kernel(const float* __restrict__ X, const float* __restrict__ g,
                          const float* __restrict__ b, __half* __restrict__ Yh) {
    int w = threadIdx.x >> 5, lane = threadIdx.x & 31;
    int row = blockIdx.x * 8 + w;
    const float* xr = X + (size_t)row * DM;
    float4 v[6];
    float s = 0.f, sq = 0.f;
#pragma unroll
    for (int i = 0; i < 6; i++) {
        v[i] = *(const float4*)(xr + i * 128 + lane * 4);
        s  += v[i].x + v[i].y + v[i].z + v[i].w;
        sq += v[i].x * v[i].x + v[i].y * v[i].y + v[i].z * v[i].z + v[i].w * v[i].w;
    }
#pragma unroll
    for (int o = 16; o > 0; o >>= 1) {
        s  += __shfl_xor_sync(0xffffffffu, s, o);
        sq += __shfl_xor_sync(0xffffffffu, sq, o);
    }
    float mu  = s * (1.f / DM);
    float var = sq * (1.f / DM) - mu * mu;
    float inv = rsqrtf(var + 1e-5f);
#pragma unroll
    for (int i = 0; i < 6; i++) {
        int idx = i * 128 + lane * 4;
        float4 gg = *(const float4*)(g + idx);
        float4 bb = *(const float4*)(b + idx);
        float y0 = (v[i].x - mu) * inv * gg.x + bb.x;
        float y1 = (v[i].y - mu) * inv * gg.y + bb.y;
        float y2 = (v[i].z - mu) * inv * gg.z + bb.z;
        float y3 = (v[i].w - mu) * inv * gg.w + bb.w;
        uint2 hp;
        hp.x = packh2(y0, y1);
        hp.y = packh2(y2, y3);
        *(uint2*)(Yh + (size_t)row * DM + idx) = hp;
    }
}

// ---------------- fp16 GEMM: BM=128, BN=128, BK=64, 2-stage, 2 CTAs/SM -----
// D = A * W, fp32 acc; plain fp16 operands; warp tile 64x32.
#define A_ST2 144
#define APLANE 18432            // 128*144
#define STG (2 * APLANE)        // 36864 (A plane + B plane)
#define GSM (2 * STG)           // 73728

template <int MODE>
__global__ void __launch_bounds__(256, 2)
gemm_fp(const __half* __restrict__ A, const __half* __restrict__ Bh,
        const float* __restrict__ bias, const float* __restrict__ res,
        float* __restrict__ C, __half* __restrict__ Ch,
        int M, int N, int K) {
    extern __shared__ char smem[];
    const uint32_t sb = smem_u32(smem);

    int tid = threadIdx.x, wid = tid >> 5, lane = tid & 31;
    int bn = blockIdx.x, bm = blockIdx.y;
    int wm = wid >> 2, wn = wid & 3;

    uint32_t a_lm = (uint32_t)((wm * 64 + (lane & 15)) * A_ST2 + ((lane >> 4) & 1) * 16);
    uint32_t b_lm = (uint32_t)((wn * 32 + (lane & 15)) * A_ST2 + ((lane >> 4) & 1) * 16);

    float acc[4][4][4];
#pragma unroll
    for (int i = 0; i < 4; i++)
#pragma unroll
        for (int j = 0; j < 4; j++)
#pragma unroll
            for (int q = 0; q < 4; q++) acc[i][j][q] = 0.f;

    const int nkt = K / 64;

    auto load_stage = [&](int kt, int buf) {
        uint32_t st = sb + buf * STG;
        const __half* a0 = A + (size_t)(bm * 128) * K + kt * 64;
        const __half* b0 = Bh + (size_t)(bn * 128) * K + kt * 64;
#pragma unroll
        for (int i = 0; i < 4; i++) {
            int c = tid + i * 256;
            int row = c >> 3, col = c & 7;
            uint32_t so = (uint32_t)(row * A_ST2 + col * 16);
            const size_t go = (size_t)row * K + col * 8;
            cp16(st + so, a0 + go);
            cp16(st + APLANE + so, b0 + go);
        }
    };

    load_stage(0, 0); CP_COMMIT();
    if (nkt > 1) { load_stage(1, 1); CP_COMMIT(); }

    for (int kt = 0; kt < nkt; kt++) {
        if (kt + 1 < nkt) { CP_WAIT(1); } else { CP_WAIT(0); }
        __syncthreads();
        uint32_t st = sb + (kt & 1) * STG;
#pragma unroll
        for (int ks = 0; ks < 4; ks++) {
            uint32_t bh[4][2];
#pragma unroll
            for (int nt2 = 0; nt2 < 2; nt2++) {
                uint32_t bo = b_lm + (uint32_t)(nt2 * 16 * A_ST2 + ks * 32);
                uint32_t th[4];
                ldsm_x4(th, st + APLANE + bo);
                bh[nt2 * 2][0] = th[0]; bh[nt2 * 2][1] = th[2];
                bh[nt2 * 2 + 1][0] = th[1]; bh[nt2 * 2 + 1][1] = th[3];
            }
#pragma unroll
            for (int mt = 0; mt < 4; mt++) {
                uint32_t ah[4];
                ldsm_x4(ah, st + a_lm + (uint32_t)(mt * 16 * A_ST2 + ks * 32));
#pragma unroll
                for (int nt = 0; nt < 4; nt++)
                    mma2(acc[mt][nt], ah, bh[nt][0], bh[nt][1]);
            }
        }
        __syncthreads();
        if (kt + 2 < nkt) {
            load_stage(kt + 2, kt & 1);
            CP_COMMIT();
        }
    }

    int r0 = bm * 128 + wm * 64 + (lane >> 2);
    int c0 = bn * 128 + wn * 32 + (lane & 3) * 2;
#pragma unroll
    for (int mt = 0; mt < 4; mt++) {
#pragma unroll
        for (int nt = 0; nt < 4; nt++) {
            int col = c0 + nt * 8;
            float bb0 = bias[col], bb1 = bias[col + 1];
#pragma unroll
            for (int half_ = 0; half_ < 2; half_++) {
                int row = r0 + mt * 16 + half_ * 8;
                float v0 = acc[mt][nt][half_ * 2 + 0] + bb0;
                float v1 = acc[mt][nt][half_ * 2 + 1] + bb1;
                if (MODE == 1) {
                    v0 = 0.5f * v0 * (1.f + erff(v0 * 0.70710678118654752f));
                    v1 = 0.5f * v1 * (1.f + erff(v1 * 0.70710678118654752f));
                    *(uint32_t*)(Ch + (size_t)row * N + col) = packh2(v0, v1);
                } else if (MODE == 2) {
                    const float* rp = res + (size_t)row * N + col;
                    float2 o; o.x = v0 + rp[0]; o.y = v1 + rp[1];
                    *(float2*)(C + (size_t)row * N + col) = o;
                } else { // MODE 3: scatter into Q/K/V fp16 planes
                    int i3 = col / DM;
                    int rem = col - i3 * DM;
                    int h = rem >> 6, d = rem & 63;
                    int bb = row >> 11, l = row & 2047;
                    size_t idx = (((size_t)bb * NH + h) * LSEQ + l) * HD + d;
                    if (i3 == 0) { v0 *= QSCALE; v1 *= QSCALE; }
                    __half* ph = (i3 == 0) ? g_qh : (i3 == 1) ? g_kh : g_vh;
                    *(uint32_t*)(ph + idx) = packh2(v0, v1);
                }
            }
        }
    }
}

// ---------------- MMA flash attention: fp16, Q tile 128, 2 CTAs/SM ---------
#define AT_ST 144
#define AT_PLANE (64 * AT_ST)          // 9216
#define AT_STAGE (2 * AT_PLANE)        // 18432 (K + V)
#define AT_SMEM (2 * AT_STAGE + 512)   // 37376
#define NT_KV (LSEQ / 64)              // 32

__global__ void __launch_bounds__(256, 2)
attn_mma(const int* __restrict__ mask, __half* __restrict__ Oh) {
    extern __shared__ char sm[];
    const uint32_t sb = smem_u32(sm);
    float* mb2 = (float*)(sm + 2 * AT_STAGE);

    int tid = threadIdx.x, wid = tid >> 5, lane = tid & 31;
    int qt = blockIdx.x, h = blockIdx.y, b = blockIdx.z;
    size_t bh = ((size_t)b * NH + h) * LSEQ * HD;
    const __half* Qp = g_qh + bh;
    const __half* Kp = g_kh + bh;
    const __half* Vp = g_vh + bh;

    {
        int qrow0 = qt * 128;
#pragma unroll
        for (int i = 0; i < 4; i++) {
            int c = tid * 4 + i;
            int row = c >> 3, col = c & 7;
            cp16(sb + (uint32_t)(row * AT_ST + col * 16),
                 Qp + (size_t)(qrow0 + row) * HD + col * 8);
        }
    }
    CP_COMMIT();
    CP_WAIT(0);
    __syncthreads();

    uint32_t qf[4][4];
    {
        uint32_t qbase = sb + (uint32_t)((wid * 16 + (lane & 15)) * AT_ST + (lane >> 4) * 16);
#pragma unroll
        for (int ks = 0; ks < 4; ks++)
            ldsm_x4(qf[ks], qbase + ks * 32);
    }
    __syncthreads();

    auto load_kv = [&](int kt, int buf) {
        uint32_t st = sb + buf * AT_STAGE;
        const __half* k0 = Kp + (size_t)kt * 64 * HD;
        const __half* v0 = Vp + (size_t)kt * 64 * HD;
#pragma unroll
        for (int i = 0; i < 2; i++) {
            int c = tid * 2 + i;
            int row = c >> 3, col = c & 7;
            uint32_t so = (uint32_t)(row * AT_ST + col * 16);
            cp16(st + so, k0 + (size_t)row * HD + col * 8);
            cp16(st + AT_PLANE + so, v0 + (size_t)row * HD + col * 8);
        }
    };

    if (tid < 64) mb2[tid] = mask[b * LSEQ + tid] ? 0.f : -1e30f;
    load_kv(0, 0);
    CP_COMMIT();

    float m0 = -1e30f, m1 = -1e30f, l0 = 0.f, l1 = 0.f;
    float o[8][4];
#pragma unroll
    for (int nt = 0; nt < 8; nt++)
#pragma unroll
        for (int q = 0; q < 4; q++) o[nt][q] = 0.f;

    for (int kt = 0; kt < NT_KV; kt++) {
        CP_WAIT(0);
        __syncthreads();
        if (kt + 1 < NT_KV) {
            if (tid < 64)
                mb2[((kt + 1) & 1) * 64 + tid] =
                    mask[b * LSEQ + (kt + 1) * 64 + tid] ? 0.f : -1e30f;
            load_kv(kt + 1, (kt + 1) & 1);
            CP_COMMIT();
        }
        uint32_t st = sb + (kt & 1) * AT_STAGE;
        const float* mrow = mb2 + (kt & 1) * 64;

        float s[8][4];
#pragma unroll
        for (int nt = 0; nt < 8; nt++)
#pragma unroll
            for (int q = 0; q < 4; q++) s[nt][q] = 0.f;

#pragma unroll
        for (int ks = 0; ks < 4; ks++) {
#pragma unroll
            for (int g = 0; g < 4; g++) {
                uint32_t addr = st + (uint32_t)((g * 16 + (lane & 15)) * AT_ST
                                                + ks * 32 + (lane >> 4) * 16);
                uint32_t t4[4];
                ldsm_x4(t4, addr);
                mma2(s[g * 2], qf[ks], t4[0], t4[2]);
                mma2(s[g * 2 + 1], qf[ks], t4[1], t4[3]);
            }
        }

        float rmax0 = -1e30f, rmax1 = -1e30f;
#pragma unroll
        for (int nt = 0; nt < 8; nt++) {
            int k0i = nt * 8 + (lane & 3) * 2;
            float mk0 = mrow[k0i], mk1 = mrow[k0i + 1];
            s[nt][0] += mk0; s[nt][1] += mk1;
            s[nt][2] += mk0; s[nt][3] += mk1;
            rmax0 = fmaxf(rmax0, fmaxf(s[nt][0], s[nt][1]));
            rmax1 = fmaxf(rmax1, fmaxf(s[nt][2], s[nt][3]));
        }
        rmax0 = fmaxf(rmax0, __shfl_xor_sync(0xffffffffu, rmax0, 1));
        rmax0 = fmaxf(rmax0, __shfl_xor_sync(0xffffffffu, rmax0, 2));
        rmax1 = fmaxf(rmax1, __shfl_xor_sync(0xffffffffu, rmax1, 1));
        rmax1 = fmaxf(rmax1, __shfl_xor_sync(0xffffffffu, rmax1, 2));
        float mn0 = fmaxf(m0, rmax0), mn1 = fmaxf(m1, rmax1);
        float al0 = ex2f(m0 - mn0), al1 = ex2f(m1 - mn1);
        m0 = mn0; m1 = mn1;
        float ps0 = 0.f, ps1 = 0.f;
#pragma unroll
        for (int nt = 0; nt < 8; nt++) {
            s[nt][0] = ex2f(s[nt][0] - m0);
            s[nt][1] = ex2f(s[nt][1] - m0);
            s[nt][2] = ex2f(s[nt][2] - m1);
            s[nt][3] = ex2f(s[nt][3] - m1);
            ps0 += s[nt][0] + s[nt][1];
            ps1 += s[nt][2] + s[nt][3];
        }
        ps0 += __shfl_xor_sync(0xffffffffu, ps0, 1);
        ps0 += __shfl_xor_sync(0xffffffffu, ps0, 2);
        ps1 += __shfl_xor_sync(0xffffffffu, ps1, 1);
        ps1 += __shfl_xor_sync(0xffffffffu, ps1, 2);
        l0 = l0 * al0 + ps0;
        l1 = l1 * al1 + ps1;
        bool need = (al0 != 1.f) || (al1 != 1.f);
        if (__ballot_sync(0xffffffffu, need)) {
#pragma unroll
            for (int nt = 0; nt < 8; nt++) {
                o[nt][0] *= al0; o[nt][1] *= al0;
                o[nt][2] *= al1; o[nt][3] *= al1;
            }
        }

        uint32_t pf[4][4];
#pragma unroll
        for (int j = 0; j < 4; j++) {
            pf[j][0] = packh2(s[2 * j][0], s[2 * j][1]);
            pf[j][1] = packh2(s[2 * j][2], s[2 * j][3]);
            pf[j][2] = packh2(s[2 * j + 1][0], s[2 * j + 1][1]);
            pf[j][3] = packh2(s[2 * j + 1][2], s[2 * j + 1][3]);
        }

        int g = lane >> 3;
#pragma unroll
        for (int j = 0; j < 4; j++) {
#pragma unroll
            for (int dt = 0; dt < 4; dt++) {
                uint32_t addr = st + (uint32_t)(AT_PLANE
                    + (j * 16 + (g >> 1) * 8 + (lane & 7)) * AT_ST
                    + dt * 32 + (g & 1) * 16);
                uint32_t t4[4];
                ldsm_x4_t(t4, addr);
                mma2(o[dt * 2], pf[j], t4[0], t4[2]);
                mma2(o[dt * 2 + 1], pf[j], t4[1], t4[3]);
            }
        }
    }

    float i0 = 1.f / l0, i1 = 1.f / l1;
    int rowg = b * LSEQ + qt * 128 + wid * 16 + (lane >> 2);
#pragma unroll
    for (int nt = 0; nt < 8; nt++) {
        int col = h * HD + nt * 8 + (lane & 3) * 2;
        *(uint32_t*)(Oh + (size_t)rowg * DM + col) = packh2(o[nt][0] * i0, o[nt][1] * i0);
        *(uint32_t*)(Oh + (size_t)(rowg + 8) * DM + col) = packh2(o[nt][2] * i1, o[nt][3] * i1);
    }
}

// ---------------- launch ----------------
template <typename T>
static T* symaddr(const void* sym) {
    void* p = nullptr;
    cudaGetSymbolAddress(&p, sym);
    return (T*)p;
}

extern "C" void kernel_launch(void* const* d_in, const int* in_sizes, int n_in,
                              void* d_out, int out_size) {
    (void)in_sizes; (void)n_in; (void)out_size;
    const float* x      = (const float*)d_in[0];
    const int*   mask   = (const int*)  d_in[1];
    const float* ln1_g  = (const float*)d_in[2];
    const float* ln1_b  = (const float*)d_in[3];
    const float* qkv_w  = (const float*)d_in[4];
    const float* qkv_b  = (const float*)d_in[5];
    const float* out_w  = (const float*)d_in[6];
    const float* out_b  = (const float*)d_in[7];
    const float* ln2_g  = (const float*)d_in[8];
    const float* ln2_b  = (const float*)d_in[9];
    const float* fc1_w  = (const float*)d_in[10];
    const float* fc1_b  = (const float*)d_in[11];
    const float* fc2_w  = (const float*)d_in[12];
    const float* fc2_b  = (const float*)d_in[13];
    float* out = (float*)d_out;

    float* p_x1  = symaddr<float>(g_x1);
    __half* p_hh  = symaddr<__half>(g_h_h);
    __half* p_ath = symaddr<__half>(g_at_h);
    __half* p_ffh = symaddr<__half>(g_ff_h);
    __half* wq_h = symaddr<__half>(g_wqkv_h);
    __half* wo_h = symaddr<__half>(g_wout_h);
    __half* w1_h = symaddr<__half>(g_wfc1_h);
    __half* w2_h = symaddr<__half>(g_wfc2_h);

    cudaFuncSetAttribute((const void*)gemm_fp<1>, cudaFuncAttributeMaxDynamicSharedMemorySize, GSM);
    cudaFuncSetAttribute((const void*)gemm_fp<2>, cudaFuncAttributeMaxDynamicSharedMemorySize, GSM);
    cudaFuncSetAttribute((const void*)gemm_fp<3>, cudaFuncAttributeMaxDynamicSharedMemorySize, GSM);
    cudaFuncSetAttribute((const void*)attn_mma, cudaFuncAttributeMaxDynamicSharedMemorySize, AT_SMEM);

    // 1. LN1 -> fp16 plane
    ln_kernel<<<MROWS / 8, 256>>>(x, ln1_g, ln1_b, p_hh);
    // 2. merged weight conversions (fp16)
    wconv_all<<<6912, 256>>>(qkv_w, out_w, fc1_w, fc2_w);
    // 3. QKV projection -> Q/K/V fp16 planes (Q scaled by 0.125*log2e)
    gemm_fp<3><<<dim3(NQKV / 128, MROWS / 128), 256, GSM>>>(
        p_hh, wq_h, qkv_b, nullptr, nullptr, nullptr, MROWS, NQKV, DM);
    // 4. MMA flash attention -> fp16 plane
    attn_mma<<<dim3(LSEQ / 128, NH, BB), 256, AT_SMEM>>>(mask, p_ath);
    // 5. output projection + residual
    gemm_fp<2><<<dim3(DM / 128, MROWS / 128), 256, GSM>>>(
        p_ath, wo_h, out_b, x, p_x1, nullptr, MROWS, DM, DM);
    // 6. LN2
    ln_kernel<<<MROWS / 8, 256>>>(p_x1, ln2_g, ln2_b, p_hh);
    // 7. fc1 + GELU -> fp16 plane
    gemm_fp<1><<<dim3(DFF / 128, MROWS / 128), 256, GSM>>>(
        p_hh, w1_h, fc1_b, nullptr, nullptr, p_ffh, MROWS, DFF, DM);
    // 8. fc2 + residual -> output
    gemm_fp<2><<<dim3(DM / 128, MROWS / 128), 256, GSM>>>(
        p_ffh, w2_h, fc2_b, p_x1, out, nullptr, MROWS, DM, DFF);
}